// round 12
// baseline (speedup 1.0000x reference)
#include <cuda_runtime.h>
#include <cuda_bf16.h>
#include <math.h>
#include <cstdint>

// ---------------- problem constants ----------------
#define BG     32
#define NPG    1024
#define DEGC   8
#define F_IN   512
#define HD     1024
#define OUTD   10
#define E_TOT  (BG*NPG*DEGC)   // 262144
#define EPG    (NPG*DEGC)      // 8192
#define N1     (BG*NPG)        // 32768
#define KP1    512
#define N2     (BG*KP1)        // 16384
#define KP2    256
#define N3     (BG*KP2)        // 8192
#define FC1D   512
#define BN_EPS 1e-5f

// ---------------- scratch layout (floats) ----------------
#define F_AGG1    ((size_t)0)
#define F_HP1     (F_AGG1 + (size_t)N1*HD)
#define F_AGG2    (F_HP1  + (size_t)N2*HD)
#define F_DINV1   (F_AGG2 + (size_t)N2*HD)
#define F_DINV2   (F_DINV1 + N1)
#define F_SCORE1  (F_DINV2 + N2)
#define F_SCORE2  (F_SCORE1 + N1)
#define F_VAL1    (F_SCORE2 + N2)
#define F_VAL2    (F_VAL1 + N2)
#define F_COLS    (F_VAL2 + N3)          // csum1,csq1,csum2,csq2 : 4*HD
#define F_SCALE1  (F_COLS + 4*HD)
#define F_SHIFT1  (F_SCALE1 + HD)
#define F_SCALE2  (F_SHIFT1 + HD)
#define F_SHIFT2  (F_SCALE2 + HD)
#define F_PN1     (F_SHIFT2 + HD)
#define F_PN2     (F_PN1 + HD)
#define F_X1      (F_PN2 + HD)
#define F_X2      (F_X1 + BG*HD)
#define F_END     (F_X2 + BG*HD)

#define I_SRC2   ((size_t)0)
#define I_DST2   (I_SRC2 + E_TOT)
#define I_CSR    (I_DST2 + E_TOT)
#define I_CNT1   (I_CSR + E_TOT)
#define I_CNT2   (I_CNT1 + N1)
#define I_OFF1   (I_CNT2 + N2)
#define I_CUR1   (I_OFF1 + N1)
#define I_OFF2   (I_CUR1 + N1)
#define I_CUR2   (I_OFF2 + N2)
#define I_PERM1  (I_CUR2 + N2)
#define I_PERM2  (I_PERM1 + N2)
#define I_NEWID  (I_PERM2 + N3)
#define I_END    (I_NEWID + N1)

__device__ float d_fscratch[F_END];
__device__ int   d_iscratch[I_END];

// A stored [hi|lo] (2K wide); B stored [hi|lo|hi] (3K wide)
__device__ __nv_bfloat16 d_a1s[(size_t)N1 * 2 * F_IN];
__device__ __nv_bfloat16 d_w1s[(size_t)HD * 3 * F_IN];
__device__ __nv_bfloat16 d_a2s[(size_t)N2 * 2 * HD];
__device__ __nv_bfloat16 d_w2s[(size_t)HD * 3 * HD];

// ================= helpers =================
__device__ __forceinline__ uint32_t smem_u32(const void* p) {
    uint32_t a;
    asm("{ .reg .u64 t; cvta.to.shared.u64 t, %1; cvt.u32.u64 %0, t; }" : "=r"(a) : "l"(p));
    return a;
}
#define SWZ128(b) ((b) ^ (((b) >> 3) & 0x70))

__device__ __forceinline__ void cp16(uint32_t dst, const void* src) {
    asm volatile("cp.async.cg.shared.global [%0], [%1], 16;" :: "r"(dst), "l"(src));
}

#define LDSM4(r0, r1, r2, r3, addr) \
    asm volatile("ldmatrix.sync.aligned.m8n8.x4.shared.b16 {%0,%1,%2,%3}, [%4];" \
                 : "=r"(r0), "=r"(r1), "=r"(r2), "=r"(r3) : "r"(addr))

#define MMA16816(d, a, b0, b1) \
    asm volatile("mma.sync.aligned.m16n8k16.row.col.f32.bf16.bf16.f32 " \
                 "{%0,%1,%2,%3}, {%4,%5,%6,%7}, {%8,%9}, {%0,%1,%2,%3};" \
                 : "+f"((d)[0]), "+f"((d)[1]), "+f"((d)[2]), "+f"((d)[3]) \
                 : "r"((a)[0]), "r"((a)[1]), "r"((a)[2]), "r"((a)[3]), \
                   "r"(b0), "r"(b1))

#define GEMM_SMEM_DYN (3 * 32768 + 1024)

// inline-BN param fetch: thread owns 4 cols starting at c0
__device__ __forceinline__ void bn_params(const float* csum, const float* csq, float invn,
                                          const float* g, const float* be, int c0,
                                          float4& sc, float4& sh) {
    float scv[4], shv[4];
    #pragma unroll
    for (int i = 0; i < 4; i++) {
        float m = csum[c0 + i] * invn;
        float v = csq[c0 + i] * invn - m * m;
        float rs = rsqrtf(v + BN_EPS) * g[c0 + i];
        scv[i] = rs; shv[i] = be[c0 + i] - m * rs;
    }
    sc = make_float4(scv[0], scv[1], scv[2], scv[3]);
    sh = make_float4(shv[0], shv[1], shv[2], shv[3]);
}

// ---- HMMA GEMM with fused column stats; A is [hi|lo] (stride KA), schedule hi,hi,lo
__global__ void __launch_bounds__(256, 2) gemm_mma(
    const __nv_bfloat16* __restrict__ A, const __nv_bfloat16* __restrict__ B,
    float* __restrict__ C, int K3, int KA,
    float* __restrict__ csum, float* __restrict__ csq)
{
    extern __shared__ char smem[];
    const uint32_t base = (smem_u32(smem) + 1023u) & ~1023u;
    const int tid = threadIdx.x, wid = tid >> 5, lane = tid & 31;
    const int m0 = blockIdx.y * 128;
    const int n0 = blockIdx.x * 128;
    const int wm = (wid & 3) * 32;
    const int wn = (wid >> 2) * 64;

    float acc[2][8][4];
    #pragma unroll
    for (int i = 0; i < 2; i++)
        #pragma unroll
        for (int j = 0; j < 8; j++)
            #pragma unroll
            for (int r = 0; r < 4; r++) acc[i][j][r] = 0.f;

    const int rA0 = (wm + (lane & 15)) * 128;
    const int cA  = (lane >> 4) * 16;
    const int rBb = (wn + ((lane >> 4) << 3) + (lane & 7)) * 128;
    const int cB  = ((lane >> 3) & 1) * 16;

    const int nStages = K3 >> 6;
    const int third = nStages / 3;
    const __nv_bfloat16* Abase = A + (size_t)m0 * KA;
    const __nv_bfloat16* Bbase = B + (size_t)n0 * K3;
    const int lrow = tid >> 3, lc8 = tid & 7;

    #pragma unroll
    for (int s = 0; s < 2; s++) {
        uint32_t dA = base + s * 32768, dB = dA + 16384;
        int ac = (s >= third) ? s - third : s;
        const __nv_bfloat16* Ab = Abase + ac * 64;
        const __nv_bfloat16* Bb = Bbase + s * 64;
        #pragma unroll
        for (int i = 0; i < 4; i++) {
            int row = lrow + i * 32;
            cp16(dA + SWZ128(row * 128 + lc8 * 16), Ab + (size_t)row * KA + lc8 * 8);
            cp16(dB + SWZ128(row * 128 + lc8 * 16), Bb + (size_t)row * K3 + lc8 * 8);
        }
        asm volatile("cp.async.commit_group;" ::: "memory");
    }

    int buf = 0, pbuf = 2;
    for (int ks = 0; ks < nStages; ks++) {
        asm volatile("cp.async.wait_group 1;" ::: "memory");
        __syncthreads();

        if (ks + 2 < nStages) {
            uint32_t dA = base + pbuf * 32768, dB = dA + 16384;
            int c = ks + 2;
            int ac = (c >= third) ? c - third : c;
            const __nv_bfloat16* Ab = Abase + ac * 64;
            const __nv_bfloat16* Bb = Bbase + c * 64;
            #pragma unroll
            for (int i = 0; i < 4; i++) {
                int row = lrow + i * 32;
                cp16(dA + SWZ128(row * 128 + lc8 * 16), Ab + (size_t)row * KA + lc8 * 8);
                cp16(dB + SWZ128(row * 128 + lc8 * 16), Bb + (size_t)row * K3 + lc8 * 8);
            }
        }
        asm volatile("cp.async.commit_group;" ::: "memory");

        const uint32_t As = base + buf * 32768;
        const uint32_t Bs = As + 16384;
        #pragma unroll
        for (int kk = 0; kk < 4; kk++) {
            const int kb = kk * 32;
            uint32_t a0[4], a1[4];
            LDSM4(a0[0], a0[1], a0[2], a0[3], As + SWZ128(rA0 + cA + kb));
            LDSM4(a1[0], a1[1], a1[2], a1[3], As + SWZ128(rA0 + 16 * 128 + cA + kb));
            uint32_t bf[4][4];
            #pragma unroll
            for (int jj = 0; jj < 4; jj++)
                LDSM4(bf[jj][0], bf[jj][1], bf[jj][2], bf[jj][3],
                      Bs + SWZ128(rBb + jj * 16 * 128 + cB + kb));
            #pragma unroll
            for (int j = 0; j < 8; j++) {
                const int jj = j >> 1, hh = (j & 1) * 2;
                MMA16816(acc[0][j], a0, bf[jj][hh], bf[jj][hh + 1]);
                MMA16816(acc[1][j], a1, bf[jj][hh], bf[jj][hh + 1]);
            }
        }
        buf = (buf == 2) ? 0 : buf + 1;
        pbuf = (pbuf == 2) ? 0 : pbuf + 1;
    }

    const int rq = lane >> 2, cq = (lane & 3) * 2;
    #pragma unroll
    for (int mi = 0; mi < 2; mi++) {
        int rowb = m0 + wm + mi * 16 + rq;
        #pragma unroll
        for (int j = 0; j < 8; j++) {
            float* p0 = C + (size_t)rowb * HD + n0 + wn + j * 8 + cq;
            *(float2*)p0 = make_float2(acc[mi][j][0], acc[mi][j][1]);
            *(float2*)(p0 + 8 * (size_t)HD) = make_float2(acc[mi][j][2], acc[mi][j][3]);
        }
    }

    // fused column stats
    #pragma unroll
    for (int j = 0; j < 8; j++) {
        float s0 = 0.f, s1 = 0.f, q0 = 0.f, q1 = 0.f;
        #pragma unroll
        for (int mi = 0; mi < 2; mi++) {
            s0 += acc[mi][j][0] + acc[mi][j][2];
            s1 += acc[mi][j][1] + acc[mi][j][3];
            q0 += acc[mi][j][0] * acc[mi][j][0] + acc[mi][j][2] * acc[mi][j][2];
            q1 += acc[mi][j][1] * acc[mi][j][1] + acc[mi][j][3] * acc[mi][j][3];
        }
        #pragma unroll
        for (int o = 16; o >= 4; o >>= 1) {
            s0 += __shfl_down_sync(0xffffffff, s0, o);
            s1 += __shfl_down_sync(0xffffffff, s1, o);
            q0 += __shfl_down_sync(0xffffffff, q0, o);
            q1 += __shfl_down_sync(0xffffffff, q1, o);
        }
        if (lane < 4) {
            int col = n0 + wn + j * 8 + lane * 2;
            atomicAdd(&csum[col], s0);
            atomicAdd(&csum[col + 1], s1);
            atomicAdd(&csq[col], q0);
            atomicAdd(&csq[col + 1], q1);
        }
    }
}

// ---- weight split (B' = [hi|lo|hi], 3K) ----
__global__ void wsplit_k(const float* __restrict__ W, __nv_bfloat16* __restrict__ O, int K) {
    int i = blockIdx.x * blockDim.x + threadIdx.x;
    int k = i >> 10, n = i & 1023;
    if (k >= K) return;
    float v = W[i];
    __nv_bfloat16 hi = __float2bfloat16(v);
    __nv_bfloat16 lo = __float2bfloat16(v - __bfloat162float(hi));
    size_t base = (size_t)n * (3 * K);
    O[base + k] = hi; O[base + K + k] = lo; O[base + 2 * K + k] = hi;
}

// ---------------- CSR build ----------------
__global__ void zero_int_k(int* p, int n) {
    int i = blockIdx.x * blockDim.x + threadIdx.x;
    if (i < n) p[i] = 0;
}

__global__ void count_k(const int* __restrict__ dstv, int* __restrict__ cnt, int n) {
    int e = blockIdx.x * blockDim.x + threadIdx.x;
    if (e < n) atomicAdd(&cnt[dstv[e]], 1);
}

__global__ void remapcount_k(const int* __restrict__ src, const int* __restrict__ dst,
                             const int* __restrict__ newid, int* __restrict__ src2,
                             int* __restrict__ dst2, int* __restrict__ cnt2, int n) {
    int e = blockIdx.x * blockDim.x + threadIdx.x;
    if (e >= n) return;
    int s = newid[src[e]], d = newid[dst[e]];
    if (s < 0 || d < 0) { src2[e] = -1; dst2[e] = 0; }
    else { src2[e] = s; dst2[e] = d; atomicAdd(&cnt2[d], 1); }
}

template<int NPGT>
__global__ void scan_off_k(const int* __restrict__ cnt, int* __restrict__ off,
                           int* __restrict__ cursor, float* __restrict__ dinv) {
    __shared__ int sh[NPGT];
    int b = blockIdx.x, t = threadIdx.x;
    int v = cnt[b * NPGT + t];
    sh[t] = v;
    dinv[b * NPGT + t] = rsqrtf(1.0f + (float)v);
    __syncthreads();
    #pragma unroll
    for (int d = 1; d < NPGT; d <<= 1) {
        int add = (t >= d) ? sh[t - d] : 0;
        __syncthreads();
        sh[t] += add;
        __syncthreads();
    }
    int o = b * EPG + sh[t] - v;
    off[b * NPGT + t] = o;
    cursor[b * NPGT + t] = o;
}

__global__ void fill_csr_k(const int* __restrict__ srcv, const int* __restrict__ dstv,
                           int* __restrict__ cursor, int* __restrict__ csr, int n, int checkValid) {
    int e = blockIdx.x * blockDim.x + threadIdx.x;
    if (e >= n) return;
    int s = srcv[e];
    if (checkValid && s < 0) return;
    int pos = atomicAdd(&cursor[dstv[e]], 1);
    csr[pos] = s;
}

// ---- layer-1 gather over X with fused bf16 [hi|lo] split output
__global__ void __launch_bounds__(128) gxsplit_k(
    const float* __restrict__ X, const int* __restrict__ csr,
    const int* __restrict__ off, const int* __restrict__ cnt,
    const float* __restrict__ dinv, __nv_bfloat16* __restrict__ As)
{
    const int n = blockIdx.x, t = threadIdx.x;
    const float iv = dinv[n];
    const int o = off[n], c = cnt[n];
    float4 l = ((const float4*)(X + (size_t)n * F_IN))[t];
    const float iv2 = iv * iv;
    float4 acc = make_float4(l.x * iv2, l.y * iv2, l.z * iv2, l.w * iv2);
    int j = 0;
    for (; j + 1 < c; j += 2) {
        int s0 = __ldg(&csr[o + j]), s1 = __ldg(&csr[o + j + 1]);
        float w0 = __ldg(&dinv[s0]) * iv, w1 = __ldg(&dinv[s1]) * iv;
        float4 v0 = ((const float4*)(X + (size_t)s0 * F_IN))[t];
        float4 v1 = ((const float4*)(X + (size_t)s1 * F_IN))[t];
        acc.x += v0.x * w0 + v1.x * w1;
        acc.y += v0.y * w0 + v1.y * w1;
        acc.z += v0.z * w0 + v1.z * w1;
        acc.w += v0.w * w0 + v1.w * w1;
    }
    if (j < c) {
        int s0 = __ldg(&csr[o + j]);
        float w0 = __ldg(&dinv[s0]) * iv;
        float4 v0 = ((const float4*)(X + (size_t)s0 * F_IN))[t];
        acc.x += v0.x * w0; acc.y += v0.y * w0;
        acc.z += v0.z * w0; acc.w += v0.w * w0;
    }
    __nv_bfloat16* rp = As + (size_t)n * (2 * F_IN);
    int k = t * 4;
    float vs[4] = {acc.x, acc.y, acc.z, acc.w};
    #pragma unroll
    for (int i = 0; i < 4; i++) {
        __nv_bfloat16 h = __float2bfloat16(vs[i]);
        rp[k + i] = h;
        rp[F_IN + k + i] = __float2bfloat16(vs[i] - __bfloat162float(h));
    }
}

// ---- layer-2 gather over hp1 with fused bf16 [hi|lo] split output
__global__ void __launch_bounds__(256) y2split_k(
    const float* __restrict__ H, const int* __restrict__ csr,
    const int* __restrict__ off, const int* __restrict__ cnt,
    const float* __restrict__ dinv, __nv_bfloat16* __restrict__ As)
{
    const int n = blockIdx.x, t = threadIdx.x;
    const float iv = dinv[n];
    const int o = off[n], c = cnt[n];
    float4 l = ((const float4*)(H + (size_t)n * HD))[t];
    const float iv2 = iv * iv;
    float4 acc = make_float4(l.x * iv2, l.y * iv2, l.z * iv2, l.w * iv2);
    int j = 0;
    for (; j + 1 < c; j += 2) {
        int s0 = __ldg(&csr[o + j]), s1 = __ldg(&csr[o + j + 1]);
        float w0 = __ldg(&dinv[s0]) * iv, w1 = __ldg(&dinv[s1]) * iv;
        float4 v0 = ((const float4*)(H + (size_t)s0 * HD))[t];
        float4 v1 = ((const float4*)(H + (size_t)s1 * HD))[t];
        acc.x += v0.x * w0 + v1.x * w1;
        acc.y += v0.y * w0 + v1.y * w1;
        acc.z += v0.z * w0 + v1.z * w1;
        acc.w += v0.w * w0 + v1.w * w1;
    }
    if (j < c) {
        int s0 = __ldg(&csr[o + j]);
        float w0 = __ldg(&dinv[s0]) * iv;
        float4 v0 = ((const float4*)(H + (size_t)s0 * HD))[t];
        acc.x += v0.x * w0; acc.y += v0.y * w0;
        acc.z += v0.z * w0; acc.w += v0.w * w0;
    }
    __nv_bfloat16* rp = As + (size_t)n * (2 * HD);
    int k = t * 4;
    float vs[4] = {acc.x, acc.y, acc.z, acc.w};
    #pragma unroll
    for (int i = 0; i < 4; i++) {
        __nv_bfloat16 h = __float2bfloat16(vs[i]);
        rp[k + i] = h;
        rp[HD + k + i] = __float2bfloat16(vs[i] - __bfloat162float(h));
    }
}

// ---------------- BN / score / pooling ----------------
__global__ void fill_k(float* p, int n, float v) {
    int i = blockIdx.x * blockDim.x + threadIdx.x;
    if (i < n) p[i] = v;
}

__global__ void bnprep_k(const float* __restrict__ csum, const float* __restrict__ csq,
                         float invn, const float* __restrict__ g, const float* __restrict__ be,
                         float* __restrict__ scale, float* __restrict__ shift) {
    int c = blockIdx.x * blockDim.x + threadIdx.x;
    float m = csum[c] * invn;
    float v = csq[c] * invn - m * m;
    float rs = rsqrtf(v + BN_EPS) * g[c];
    scale[c] = rs;
    shift[c] = be[c] - m * rs;
}

__global__ void pnorm_k(const float* __restrict__ p, float* __restrict__ pn) {
    int t = threadIdx.x;
    float v = p[t];
    float s = v * v;
    #pragma unroll
    for (int o = 16; o > 0; o >>= 1) s += __shfl_down_sync(0xffffffff, s, o);
    __shared__ float red[32];
    if ((t & 31) == 0) red[t >> 5] = s;
    __syncthreads();
    if (t < 32) {
        float x = red[t];
        #pragma unroll
        for (int o = 16; o > 0; o >>= 1) x += __shfl_down_sync(0xffffffff, x, o);
        if (t == 0) red[0] = x;
    }
    __syncthreads();
    pn[t] = v * rsqrtf(red[0]);
}

// score with inline BN (no scale/shift dependency)
__global__ void score_k(const float* __restrict__ X,
                        const float* __restrict__ csum, const float* __restrict__ csq, float invn,
                        const float* __restrict__ g, const float* __restrict__ be,
                        const float* __restrict__ pn, float* __restrict__ score) {
    int row = blockIdx.x, t = threadIdx.x;
    float4 sc, sh;
    bn_params(csum, csq, invn, g, be, t * 4, sc, sh);
    size_t base = (size_t)row * HD + t * 4;
    float4 v = *(const float4*)&X[base];
    v.x = fmaxf(fmaf(v.x, sc.x, sh.x), 0.f);
    v.y = fmaxf(fmaf(v.y, sc.y, sh.y), 0.f);
    v.z = fmaxf(fmaf(v.z, sc.z, sh.z), 0.f);
    v.w = fmaxf(fmaf(v.w, sc.w, sh.w), 0.f);
    float4 p = *(const float4*)&pn[t * 4];
    float dot = v.x * p.x + v.y * p.y + v.z * p.z + v.w * p.w;
    #pragma unroll
    for (int o = 16; o > 0; o >>= 1) dot += __shfl_down_sync(0xffffffff, dot, o);
    __shared__ float red[8];
    if ((t & 31) == 0) red[t >> 5] = dot;
    __syncthreads();
    if (t == 0) {
        float s = 0.f;
        #pragma unroll
        for (int i = 0; i < 8; i++) s += red[i];
        score[row] = tanhf(s);
    }
}

template<int NPGT, int KK>
__global__ void topk_k(const float* __restrict__ score, float* __restrict__ val,
                       int* __restrict__ perm, int* __restrict__ newid) {
    __shared__ float s[NPGT];
    __shared__ int   id[NPGT];
    int b = blockIdx.x, t = threadIdx.x;
    s[t] = score[b * NPGT + t];
    id[t] = t;
    for (int size = 2; size <= NPGT; size <<= 1) {
        for (int stride = size >> 1; stride > 0; stride >>= 1) {
            __syncthreads();
            int j = t ^ stride;
            if (j > t) {
                float a = s[t], c = s[j];
                int ia = id[t], ic = id[j];
                bool aFirst = (a > c) || (a == c && ia < ic);
                bool descHere = ((t & size) == 0);
                if (descHere ? !aFirst : aFirst) {
                    s[t] = c; s[j] = a; id[t] = ic; id[j] = ia;
                }
            }
        }
    }
    __syncthreads();
    if (t < KK) {
        perm[b * KK + t] = b * NPGT + id[t];
        val[b * KK + t] = s[t];
        if (newid) newid[b * NPGT + id[t]] = b * KK + t;
    } else if (newid) {
        newid[b * NPGT + id[t]] = -1;
    }
}

// lazy BN+ReLU gather: hp[row] = relu(agg[perm]*sc+sh) * val
__global__ void gather_bn_k(const float* __restrict__ Hin, const int* __restrict__ perm,
                            const float* __restrict__ val,
                            const float* __restrict__ scale, const float* __restrict__ shift,
                            float* __restrict__ Hout) {
    int row = blockIdx.x, t = threadIdx.x;
    int srow = perm[row];
    float v = val[row];
    float4 x = *(const float4*)&Hin[(size_t)srow * HD + t * 4];
    float4 sc = *(const float4*)&scale[t * 4];
    float4 sh = *(const float4*)&shift[t * 4];
    x.x = fmaxf(fmaf(x.x, sc.x, sh.x), 0.f) * v;
    x.y = fmaxf(fmaf(x.y, sc.y, sh.y), 0.f) * v;
    x.z = fmaxf(fmaf(x.z, sc.z, sh.z), 0.f) * v;
    x.w = fmaxf(fmaf(x.w, sc.w, sh.w), 0.f) * v;
    *(float4*)&Hout[(size_t)row * HD + t * 4] = x;
}

__global__ void meanpool_k(const float* __restrict__ Hin, float* __restrict__ out, int kpg) {
    int b = blockIdx.x;
    int c = blockIdx.y * 256 + threadIdx.x;
    float sum = 0.f;
    const float* p = Hin + (size_t)b * kpg * HD + c;
    for (int r = 0; r < kpg; r++) sum += p[(size_t)r * HD];
    out[b * HD + c] = sum / (float)kpg;
}

// fused layer-2 gather_bn + meanpool
__global__ void gpool2_k(const float* __restrict__ agg2, const int* __restrict__ perm,
                         const float* __restrict__ val,
                         const float* __restrict__ scale, const float* __restrict__ shift,
                         float* __restrict__ x2out) {
    int b = blockIdx.x;
    int c = blockIdx.y * 256 + threadIdx.x;
    float sc = scale[c], sh = shift[c];
    float sum = 0.f;
    #pragma unroll 4
    for (int r = 0; r < KP2; r++) {
        int srow = __ldg(&perm[b * KP2 + r]);
        float v = __ldg(&val[b * KP2 + r]);
        float xx = __ldg(&agg2[(size_t)srow * HD + c]);
        sum += fmaxf(fmaf(xx, sc, sh), 0.f) * v;
    }
    x2out[b * HD + c] = sum * (1.0f / (float)KP2);
}

// fused head: z = relu((x1+x2)@Wf + bf) ; out = z@Wf1 + bf1  (one block per graph)
__global__ void fchead_k(const float* __restrict__ x1, const float* __restrict__ x2,
                         const float* __restrict__ Wf, const float* __restrict__ bf,
                         const float* __restrict__ Wf1, const float* __restrict__ bf1,
                         float* __restrict__ out) {
    __shared__ float xs[HD];
    __shared__ float zs[FC1D];
    int m = blockIdx.x, c = threadIdx.x;
    xs[c]       = x1[m * HD + c]       + x2[m * HD + c];
    xs[c + 512] = x1[m * HD + c + 512] + x2[m * HD + c + 512];
    __syncthreads();
    float s = bf[c];
    #pragma unroll 4
    for (int k = 0; k < HD; k++) s += xs[k] * Wf[(size_t)k * FC1D + c];
    zs[c] = fmaxf(s, 0.f);
    __syncthreads();
    if (c < OUTD) {
        float o = bf1[c];
        #pragma unroll 4
        for (int k = 0; k < FC1D; k++) o += zs[k] * Wf1[k * OUTD + c];
        out[m * OUTD + c] = o;
    }
}

// ---------------- launch ----------------
extern "C" void kernel_launch(void* const* d_in, const int* in_sizes, int n_in,
                              void* d_out, int out_size) {
    (void)in_sizes; (void)n_in; (void)out_size;
    float* FS = nullptr; int* IS = nullptr;
    __nv_bfloat16 *a1s = nullptr, *w1s = nullptr, *a2s = nullptr, *w2s = nullptr;
    cudaGetSymbolAddress((void**)&FS, d_fscratch);
    cudaGetSymbolAddress((void**)&IS, d_iscratch);
    cudaGetSymbolAddress((void**)&a1s, d_a1s);
    cudaGetSymbolAddress((void**)&w1s, d_w1s);
    cudaGetSymbolAddress((void**)&a2s, d_a2s);
    cudaGetSymbolAddress((void**)&w2s, d_w2s);
    cudaFuncSetAttribute(gemm_mma, cudaFuncAttributeMaxDynamicSharedMemorySize, GEMM_SMEM_DYN);

    static cudaStream_t sB = nullptr;
    static cudaEvent_t eF = nullptr, eB1 = nullptr, eT1 = nullptr, eG1 = nullptr,
                       eB2 = nullptr, eMP = nullptr, eGM1 = nullptr, eBN1 = nullptr,
                       eGM2 = nullptr, eBN2 = nullptr;
    if (!sB) {
        cudaStreamCreateWithFlags(&sB, cudaStreamNonBlocking);
        cudaEventCreateWithFlags(&eF,   cudaEventDisableTiming);
        cudaEventCreateWithFlags(&eB1,  cudaEventDisableTiming);
        cudaEventCreateWithFlags(&eT1,  cudaEventDisableTiming);
        cudaEventCreateWithFlags(&eG1,  cudaEventDisableTiming);
        cudaEventCreateWithFlags(&eB2,  cudaEventDisableTiming);
        cudaEventCreateWithFlags(&eMP,  cudaEventDisableTiming);
        cudaEventCreateWithFlags(&eGM1, cudaEventDisableTiming);
        cudaEventCreateWithFlags(&eBN1, cudaEventDisableTiming);
        cudaEventCreateWithFlags(&eGM2, cudaEventDisableTiming);
        cudaEventCreateWithFlags(&eBN2, cudaEventDisableTiming);
    }

    const float* x   = (const float*)d_in[0];
    const int*   ei  = (const int*)d_in[1];
    const float* W1  = (const float*)d_in[3];
    const float* g1  = (const float*)d_in[5];
    const float* be1 = (const float*)d_in[6];
    const float* p1  = (const float*)d_in[7];
    const float* W2  = (const float*)d_in[8];
    const float* g2  = (const float*)d_in[10];
    const float* be2 = (const float*)d_in[11];
    const float* p2  = (const float*)d_in[12];
    const float* Wf  = (const float*)d_in[13];
    const float* bf  = (const float*)d_in[14];
    const float* Wf1 = (const float*)d_in[15];
    const float* bf1 = (const float*)d_in[16];
    float* out = (float*)d_out;

    const int* src = ei;
    const int* dst = ei + E_TOT;

    float* agg1  = FS + F_AGG1;
    float* hp1   = FS + F_HP1;
    float* agg2  = FS + F_AGG2;
    float* dinv1 = FS + F_DINV1;
    float* dinv2 = FS + F_DINV2;
    float* score1= FS + F_SCORE1;
    float* score2= FS + F_SCORE2;
    float* val1  = FS + F_VAL1;
    float* val2  = FS + F_VAL2;
    float* cols  = FS + F_COLS;
    float* csum1 = cols, *csq1 = cols + HD, *csum2 = cols + 2 * HD, *csq2 = cols + 3 * HD;
    float* scale1= FS + F_SCALE1;
    float* shift1= FS + F_SHIFT1;
    float* scale2= FS + F_SCALE2;
    float* shift2= FS + F_SHIFT2;
    float* pn1   = FS + F_PN1;
    float* pn2   = FS + F_PN2;
    float* x1    = FS + F_X1;
    float* x2    = FS + F_X2;

    int* src2  = IS + I_SRC2;
    int* dst2  = IS + I_DST2;
    int* csr   = IS + I_CSR;
    int* cnt1  = IS + I_CNT1;
    int* cnt2  = IS + I_CNT2;
    int* off1  = IS + I_OFF1;
    int* cur1  = IS + I_CUR1;
    int* off2  = IS + I_OFF2;
    int* cur2  = IS + I_CUR2;
    int* perm1 = IS + I_PERM1;
    int* perm2 = IS + I_PERM2;
    int* newid = IS + I_NEWID;

    const float invn1 = 1.0f / (float)N1;
    const float invn2 = 1.0f / (float)N2;

    // ===== fork: side stream: weight splits + pnorms + colsum zero =====
    cudaEventRecord(eF, 0);
    cudaStreamWaitEvent(sB, eF, 0);
    wsplit_k<<<(F_IN * HD) / 256, 256, 0, sB>>>(W1, w1s, F_IN);
    wsplit_k<<<(HD * HD) / 256, 256, 0, sB>>>(W2, w2s, HD);
    fill_k<<<(4 * HD) / 256, 256, 0, sB>>>(cols, 4 * HD, 0.f);
    pnorm_k<<<1, HD, 0, sB>>>(p1, pn1);
    pnorm_k<<<1, HD, 0, sB>>>(p2, pn2);
    cudaEventRecord(eB1, sB);

    // ===== main: CSR1 -> gather+split(X) -> GEMM1 =====
    zero_int_k<<<(N1 + N2 + 255) / 256, 256>>>(cnt1, N1 + N2);
    count_k<<<E_TOT / 256, 256>>>(dst, cnt1, E_TOT);
    scan_off_k<NPG><<<BG, NPG>>>(cnt1, off1, cur1, dinv1);
    fill_csr_k<<<E_TOT / 256, 256>>>(src, dst, cur1, csr, E_TOT, 0);
    gxsplit_k<<<N1, 128>>>(x, csr, off1, cnt1, dinv1, a1s);
    cudaStreamWaitEvent(0, eB1, 0);
    gemm_mma<<<dim3(HD / 128, N1 / 128), 256, GEMM_SMEM_DYN>>>(
        a1s, w1s, agg1, 3 * F_IN, 2 * F_IN, csum1, csq1);
    cudaEventRecord(eGM1, 0);

    // side: bnprep1 overlaps score1/topk1
    cudaStreamWaitEvent(sB, eGM1, 0);
    bnprep_k<<<HD / 256, 256, 0, sB>>>(csum1, csq1, invn1, g1, be1, scale1, shift1);
    cudaEventRecord(eBN1, sB);

    score_k<<<N1, 256>>>(agg1, csum1, csq1, invn1, g1, be1, pn1, score1);
    topk_k<NPG, KP1><<<BG, NPG>>>(score1, val1, perm1, newid);
    cudaEventRecord(eT1, 0);

    // side: CSR for layer 2
    cudaStreamWaitEvent(sB, eT1, 0);
    remapcount_k<<<E_TOT / 256, 256, 0, sB>>>(src, dst, newid, src2, dst2, cnt2, E_TOT);
    scan_off_k<KP1><<<BG, KP1, 0, sB>>>(cnt2, off2, cur2, dinv2);
    fill_csr_k<<<E_TOT / 256, 256, 0, sB>>>(src2, dst2, cur2, csr, E_TOT, 1);
    cudaEventRecord(eB2, sB);

    cudaStreamWaitEvent(0, eBN1, 0);
    gather_bn_k<<<N2, 256>>>(agg1, perm1, val1, scale1, shift1, hp1);
    cudaEventRecord(eG1, 0);
    // meanpool1 on side stream
    cudaStreamWaitEvent(sB, eG1, 0);
    meanpool_k<<<dim3(BG, HD / 256), 256, 0, sB>>>(hp1, x1, KP1);
    cudaEventRecord(eMP, sB);

    // ===== layer 2 =====
    cudaStreamWaitEvent(0, eB2, 0);
    y2split_k<<<N2, 256>>>(hp1, csr, off2, cnt2, dinv2, a2s);
    gemm_mma<<<dim3(HD / 128, N2 / 128), 256, GEMM_SMEM_DYN>>>(
        a2s, w2s, agg2, 3 * HD, 2 * HD, csum2, csq2);
    cudaEventRecord(eGM2, 0);

    // side: bnprep2 overlaps score2/topk2
    cudaStreamWaitEvent(sB, eGM2, 0);
    bnprep_k<<<HD / 256, 256, 0, sB>>>(csum2, csq2, invn2, g2, be2, scale2, shift2);
    cudaEventRecord(eBN2, sB);

    score_k<<<N2, 256>>>(agg2, csum2, csq2, invn2, g2, be2, pn2, score2);
    topk_k<KP1, KP2><<<BG, KP1>>>(score2, val2, perm2, nullptr);
    cudaStreamWaitEvent(0, eBN2, 0);
    gpool2_k<<<dim3(BG, HD / 256), 256>>>(agg2, perm2, val2, scale2, shift2, x2);

    // ===== Head (fused) =====
    cudaStreamWaitEvent(0, eMP, 0);
    fchead_k<<<BG, FC1D>>>(x1, x2, Wf, bf, Wf1, bf1, out);
}

// round 13
// speedup vs baseline: 1.0395x; 1.0395x over previous
#include <cuda_runtime.h>
#include <cuda_bf16.h>
#include <math.h>
#include <cstdint>

// ---------------- problem constants ----------------
#define BG     32
#define NPG    1024
#define DEGC   8
#define F_IN   512
#define HD     1024
#define OUTD   10
#define E_TOT  (BG*NPG*DEGC)   // 262144
#define EPG    (NPG*DEGC)      // 8192
#define N1     (BG*NPG)        // 32768
#define KP1    512
#define N2     (BG*KP1)        // 16384
#define KP2    256
#define N3     (BG*KP2)        // 8192
#define FC1D   512
#define BN_EPS 1e-5f

// ---------------- scratch layout (floats) ----------------
#define F_AGG1    ((size_t)0)
#define F_HP1     (F_AGG1 + (size_t)N1*HD)
#define F_AGG2    (F_HP1  + (size_t)N2*HD)
#define F_DINV1   (F_AGG2 + (size_t)N2*HD)
#define F_DINV2   (F_DINV1 + N1)
#define F_SCORE1  (F_DINV2 + N2)
#define F_SCORE2  (F_SCORE1 + N1)
#define F_VAL1    (F_SCORE2 + N2)
#define F_VAL2    (F_VAL1 + N2)
#define F_COLS    (F_VAL2 + N3)          // csum1,csq1,csum2,csq2 : 4*HD
#define F_SCALE   (F_COLS + 4*HD)
#define F_SHIFT   (F_SCALE + HD)
#define F_PN1     (F_SHIFT + HD)
#define F_PN2     (F_PN1 + HD)
#define F_X1      (F_PN2 + HD)
#define F_X2      (F_X1 + BG*HD)
#define F_END     (F_X2 + BG*HD)

#define I_SRC2   ((size_t)0)
#define I_DST2   (I_SRC2 + E_TOT)
#define I_CSR    (I_DST2 + E_TOT)
#define I_CNT1   (I_CSR + E_TOT)
#define I_CNT2   (I_CNT1 + N1)
#define I_OFF1   (I_CNT2 + N2)
#define I_CUR1   (I_OFF1 + N1)
#define I_OFF2   (I_CUR1 + N1)
#define I_CUR2   (I_OFF2 + N2)
#define I_PERM1  (I_CUR2 + N2)
#define I_PERM2  (I_PERM1 + N2)
#define I_NEWID  (I_PERM2 + N3)
#define I_END    (I_NEWID + N1)

__device__ float d_fscratch[F_END];
__device__ int   d_iscratch[I_END];

// A stored [hi|lo] (2K wide); B stored [hi|lo|hi] (3K wide)
__device__ __nv_bfloat16 d_a1s[(size_t)N1 * 2 * F_IN];
__device__ __nv_bfloat16 d_w1s[(size_t)HD * 3 * F_IN];
__device__ __nv_bfloat16 d_a2s[(size_t)N2 * 2 * HD];
__device__ __nv_bfloat16 d_w2s[(size_t)HD * 3 * HD];

// ================= helpers =================
__device__ __forceinline__ uint32_t smem_u32(const void* p) {
    uint32_t a;
    asm("{ .reg .u64 t; cvta.to.shared.u64 t, %1; cvt.u32.u64 %0, t; }" : "=r"(a) : "l"(p));
    return a;
}
#define SWZ128(b) ((b) ^ (((b) >> 3) & 0x70))

__device__ __forceinline__ void cp16(uint32_t dst, const void* src) {
    asm volatile("cp.async.cg.shared.global [%0], [%1], 16;" :: "r"(dst), "l"(src));
}

#define LDSM4(r0, r1, r2, r3, addr) \
    asm volatile("ldmatrix.sync.aligned.m8n8.x4.shared.b16 {%0,%1,%2,%3}, [%4];" \
                 : "=r"(r0), "=r"(r1), "=r"(r2), "=r"(r3) : "r"(addr))

#define MMA16816(d, a, b0, b1) \
    asm volatile("mma.sync.aligned.m16n8k16.row.col.f32.bf16.bf16.f32 " \
                 "{%0,%1,%2,%3}, {%4,%5,%6,%7}, {%8,%9}, {%0,%1,%2,%3};" \
                 : "+f"((d)[0]), "+f"((d)[1]), "+f"((d)[2]), "+f"((d)[3]) \
                 : "r"((a)[0]), "r"((a)[1]), "r"((a)[2]), "r"((a)[3]), \
                   "r"(b0), "r"(b1))

#define GEMM_SMEM_DYN (3 * 32768 + 1024)

// ---- HMMA GEMM with fused column stats; A is [hi|lo] (stride KA), schedule hi,hi,lo
__global__ void __launch_bounds__(256, 2) gemm_mma(
    const __nv_bfloat16* __restrict__ A, const __nv_bfloat16* __restrict__ B,
    float* __restrict__ C, int K3, int KA,
    float* __restrict__ csum, float* __restrict__ csq)
{
    extern __shared__ char smem[];
    const uint32_t base = (smem_u32(smem) + 1023u) & ~1023u;
    const int tid = threadIdx.x, wid = tid >> 5, lane = tid & 31;
    const int m0 = blockIdx.y * 128;
    const int n0 = blockIdx.x * 128;
    const int wm = (wid & 3) * 32;
    const int wn = (wid >> 2) * 64;

    float acc[2][8][4];
    #pragma unroll
    for (int i = 0; i < 2; i++)
        #pragma unroll
        for (int j = 0; j < 8; j++)
            #pragma unroll
            for (int r = 0; r < 4; r++) acc[i][j][r] = 0.f;

    const int rA0 = (wm + (lane & 15)) * 128;
    const int cA  = (lane >> 4) * 16;
    const int rBb = (wn + ((lane >> 4) << 3) + (lane & 7)) * 128;
    const int cB  = ((lane >> 3) & 1) * 16;

    const int nStages = K3 >> 6;
    const int third = nStages / 3;
    const __nv_bfloat16* Abase = A + (size_t)m0 * KA;
    const __nv_bfloat16* Bbase = B + (size_t)n0 * K3;
    const int lrow = tid >> 3, lc8 = tid & 7;

    #pragma unroll
    for (int s = 0; s < 2; s++) {
        uint32_t dA = base + s * 32768, dB = dA + 16384;
        int ac = (s >= third) ? s - third : s;
        const __nv_bfloat16* Ab = Abase + ac * 64;
        const __nv_bfloat16* Bb = Bbase + s * 64;
        #pragma unroll
        for (int i = 0; i < 4; i++) {
            int row = lrow + i * 32;
            cp16(dA + SWZ128(row * 128 + lc8 * 16), Ab + (size_t)row * KA + lc8 * 8);
            cp16(dB + SWZ128(row * 128 + lc8 * 16), Bb + (size_t)row * K3 + lc8 * 8);
        }
        asm volatile("cp.async.commit_group;" ::: "memory");
    }

    int buf = 0, pbuf = 2;
    for (int ks = 0; ks < nStages; ks++) {
        asm volatile("cp.async.wait_group 1;" ::: "memory");
        __syncthreads();

        if (ks + 2 < nStages) {
            uint32_t dA = base + pbuf * 32768, dB = dA + 16384;
            int c = ks + 2;
            int ac = (c >= third) ? c - third : c;
            const __nv_bfloat16* Ab = Abase + ac * 64;
            const __nv_bfloat16* Bb = Bbase + c * 64;
            #pragma unroll
            for (int i = 0; i < 4; i++) {
                int row = lrow + i * 32;
                cp16(dA + SWZ128(row * 128 + lc8 * 16), Ab + (size_t)row * KA + lc8 * 8);
                cp16(dB + SWZ128(row * 128 + lc8 * 16), Bb + (size_t)row * K3 + lc8 * 8);
            }
        }
        asm volatile("cp.async.commit_group;" ::: "memory");

        const uint32_t As = base + buf * 32768;
        const uint32_t Bs = As + 16384;
        #pragma unroll
        for (int kk = 0; kk < 4; kk++) {
            const int kb = kk * 32;
            uint32_t a0[4], a1[4];
            LDSM4(a0[0], a0[1], a0[2], a0[3], As + SWZ128(rA0 + cA + kb));
            LDSM4(a1[0], a1[1], a1[2], a1[3], As + SWZ128(rA0 + 16 * 128 + cA + kb));
            uint32_t bf[4][4];
            #pragma unroll
            for (int jj = 0; jj < 4; jj++)
                LDSM4(bf[jj][0], bf[jj][1], bf[jj][2], bf[jj][3],
                      Bs + SWZ128(rBb + jj * 16 * 128 + cB + kb));
            #pragma unroll
            for (int j = 0; j < 8; j++) {
                const int jj = j >> 1, hh = (j & 1) * 2;
                MMA16816(acc[0][j], a0, bf[jj][hh], bf[jj][hh + 1]);
                MMA16816(acc[1][j], a1, bf[jj][hh], bf[jj][hh + 1]);
            }
        }
        buf = (buf == 2) ? 0 : buf + 1;
        pbuf = (pbuf == 2) ? 0 : pbuf + 1;
    }

    const int rq = lane >> 2, cq = (lane & 3) * 2;
    #pragma unroll
    for (int mi = 0; mi < 2; mi++) {
        int rowb = m0 + wm + mi * 16 + rq;
        #pragma unroll
        for (int j = 0; j < 8; j++) {
            float* p0 = C + (size_t)rowb * HD + n0 + wn + j * 8 + cq;
            *(float2*)p0 = make_float2(acc[mi][j][0], acc[mi][j][1]);
            *(float2*)(p0 + 8 * (size_t)HD) = make_float2(acc[mi][j][2], acc[mi][j][3]);
        }
    }

    // fused column stats
    #pragma unroll
    for (int j = 0; j < 8; j++) {
        float s0 = 0.f, s1 = 0.f, q0 = 0.f, q1 = 0.f;
        #pragma unroll
        for (int mi = 0; mi < 2; mi++) {
            s0 += acc[mi][j][0] + acc[mi][j][2];
            s1 += acc[mi][j][1] + acc[mi][j][3];
            q0 += acc[mi][j][0] * acc[mi][j][0] + acc[mi][j][2] * acc[mi][j][2];
            q1 += acc[mi][j][1] * acc[mi][j][1] + acc[mi][j][3] * acc[mi][j][3];
        }
        #pragma unroll
        for (int o = 16; o >= 4; o >>= 1) {
            s0 += __shfl_down_sync(0xffffffff, s0, o);
            s1 += __shfl_down_sync(0xffffffff, s1, o);
            q0 += __shfl_down_sync(0xffffffff, q0, o);
            q1 += __shfl_down_sync(0xffffffff, q1, o);
        }
        if (lane < 4) {
            int col = n0 + wn + j * 8 + lane * 2;
            atomicAdd(&csum[col], s0);
            atomicAdd(&csum[col + 1], s1);
            atomicAdd(&csq[col], q0);
            atomicAdd(&csq[col + 1], q1);
        }
    }
}

// ---- weight split (B' = [hi|lo|hi], 3K) ----
__global__ void wsplit_k(const float* __restrict__ W, __nv_bfloat16* __restrict__ O, int K) {
    int i = blockIdx.x * blockDim.x + threadIdx.x;
    int k = i >> 10, n = i & 1023;
    if (k >= K) return;
    float v = W[i];
    __nv_bfloat16 hi = __float2bfloat16(v);
    __nv_bfloat16 lo = __float2bfloat16(v - __bfloat162float(hi));
    size_t base = (size_t)n * (3 * K);
    O[base + k] = hi; O[base + K + k] = lo; O[base + 2 * K + k] = hi;
}

// ---------------- CSR build ----------------
__global__ void zero_int_k(int* p, int n) {
    int i = blockIdx.x * blockDim.x + threadIdx.x;
    if (i < n) p[i] = 0;
}

__global__ void count_k(const int* __restrict__ dstv, int* __restrict__ cnt, int n) {
    int e = blockIdx.x * blockDim.x + threadIdx.x;
    if (e < n) atomicAdd(&cnt[dstv[e]], 1);
}

__global__ void remapcount_k(const int* __restrict__ src, const int* __restrict__ dst,
                             const int* __restrict__ newid, int* __restrict__ src2,
                             int* __restrict__ dst2, int* __restrict__ cnt2, int n) {
    int e = blockIdx.x * blockDim.x + threadIdx.x;
    if (e >= n) return;
    int s = newid[src[e]], d = newid[dst[e]];
    if (s < 0 || d < 0) { src2[e] = -1; dst2[e] = 0; }
    else { src2[e] = s; dst2[e] = d; atomicAdd(&cnt2[d], 1); }
}

template<int NPGT>
__global__ void scan_off_k(const int* __restrict__ cnt, int* __restrict__ off,
                           int* __restrict__ cursor, float* __restrict__ dinv) {
    __shared__ int sh[NPGT];
    int b = blockIdx.x, t = threadIdx.x;
    int v = cnt[b * NPGT + t];
    sh[t] = v;
    dinv[b * NPGT + t] = rsqrtf(1.0f + (float)v);
    __syncthreads();
    #pragma unroll
    for (int d = 1; d < NPGT; d <<= 1) {
        int add = (t >= d) ? sh[t - d] : 0;
        __syncthreads();
        sh[t] += add;
        __syncthreads();
    }
    int o = b * EPG + sh[t] - v;
    off[b * NPGT + t] = o;
    cursor[b * NPGT + t] = o;
}

__global__ void fill_csr_k(const int* __restrict__ srcv, const int* __restrict__ dstv,
                           int* __restrict__ cursor, int* __restrict__ csr, int n, int checkValid) {
    int e = blockIdx.x * blockDim.x + threadIdx.x;
    if (e >= n) return;
    int s = srcv[e];
    if (checkValid && s < 0) return;
    int pos = atomicAdd(&cursor[dstv[e]], 1);
    csr[pos] = s;
}

// ---- layer-1 gather over X with fused bf16 [hi|lo] split output
__global__ void __launch_bounds__(128) gxsplit_k(
    const float* __restrict__ X, const int* __restrict__ csr,
    const int* __restrict__ off, const int* __restrict__ cnt,
    const float* __restrict__ dinv, __nv_bfloat16* __restrict__ As)
{
    const int n = blockIdx.x, t = threadIdx.x;
    const float iv = dinv[n];
    const int o = off[n], c = cnt[n];
    float4 l = ((const float4*)(X + (size_t)n * F_IN))[t];
    const float iv2 = iv * iv;
    float4 acc = make_float4(l.x * iv2, l.y * iv2, l.z * iv2, l.w * iv2);
    int j = 0;
    for (; j + 1 < c; j += 2) {
        int s0 = __ldg(&csr[o + j]), s1 = __ldg(&csr[o + j + 1]);
        float w0 = __ldg(&dinv[s0]) * iv, w1 = __ldg(&dinv[s1]) * iv;
        float4 v0 = ((const float4*)(X + (size_t)s0 * F_IN))[t];
        float4 v1 = ((const float4*)(X + (size_t)s1 * F_IN))[t];
        acc.x += v0.x * w0 + v1.x * w1;
        acc.y += v0.y * w0 + v1.y * w1;
        acc.z += v0.z * w0 + v1.z * w1;
        acc.w += v0.w * w0 + v1.w * w1;
    }
    if (j < c) {
        int s0 = __ldg(&csr[o + j]);
        float w0 = __ldg(&dinv[s0]) * iv;
        float4 v0 = ((const float4*)(X + (size_t)s0 * F_IN))[t];
        acc.x += v0.x * w0; acc.y += v0.y * w0;
        acc.z += v0.z * w0; acc.w += v0.w * w0;
    }
    __nv_bfloat16* rp = As + (size_t)n * (2 * F_IN);
    int k = t * 4;
    float vs[4] = {acc.x, acc.y, acc.z, acc.w};
    #pragma unroll
    for (int i = 0; i < 4; i++) {
        __nv_bfloat16 h = __float2bfloat16(vs[i]);
        rp[k + i] = h;
        rp[F_IN + k + i] = __float2bfloat16(vs[i] - __bfloat162float(h));
    }
}

// ---- layer-2 gather over hp1 with fused bf16 [hi|lo] split output
__global__ void __launch_bounds__(256) y2split_k(
    const float* __restrict__ H, const int* __restrict__ csr,
    const int* __restrict__ off, const int* __restrict__ cnt,
    const float* __restrict__ dinv, __nv_bfloat16* __restrict__ As)
{
    const int n = blockIdx.x, t = threadIdx.x;
    const float iv = dinv[n];
    const int o = off[n], c = cnt[n];
    float4 l = ((const float4*)(H + (size_t)n * HD))[t];
    const float iv2 = iv * iv;
    float4 acc = make_float4(l.x * iv2, l.y * iv2, l.z * iv2, l.w * iv2);
    int j = 0;
    for (; j + 1 < c; j += 2) {
        int s0 = __ldg(&csr[o + j]), s1 = __ldg(&csr[o + j + 1]);
        float w0 = __ldg(&dinv[s0]) * iv, w1 = __ldg(&dinv[s1]) * iv;
        float4 v0 = ((const float4*)(H + (size_t)s0 * HD))[t];
        float4 v1 = ((const float4*)(H + (size_t)s1 * HD))[t];
        acc.x += v0.x * w0 + v1.x * w1;
        acc.y += v0.y * w0 + v1.y * w1;
        acc.z += v0.z * w0 + v1.z * w1;
        acc.w += v0.w * w0 + v1.w * w1;
    }
    if (j < c) {
        int s0 = __ldg(&csr[o + j]);
        float w0 = __ldg(&dinv[s0]) * iv;
        float4 v0 = ((const float4*)(H + (size_t)s0 * HD))[t];
        acc.x += v0.x * w0; acc.y += v0.y * w0;
        acc.z += v0.z * w0; acc.w += v0.w * w0;
    }
    __nv_bfloat16* rp = As + (size_t)n * (2 * HD);
    int k = t * 4;
    float vs[4] = {acc.x, acc.y, acc.z, acc.w};
    #pragma unroll
    for (int i = 0; i < 4; i++) {
        __nv_bfloat16 h = __float2bfloat16(vs[i]);
        rp[k + i] = h;
        rp[HD + k + i] = __float2bfloat16(vs[i] - __bfloat162float(h));
    }
}

// ---------------- BN / score / pooling ----------------
__global__ void fill_k(float* p, int n, float v) {
    int i = blockIdx.x * blockDim.x + threadIdx.x;
    if (i < n) p[i] = v;
}

__global__ void bnprep_k(const float* __restrict__ csum, const float* __restrict__ csq,
                         float invn, const float* __restrict__ g, const float* __restrict__ be,
                         float* __restrict__ scale, float* __restrict__ shift) {
    int c = blockIdx.x * blockDim.x + threadIdx.x;
    float m = csum[c] * invn;
    float v = csq[c] * invn - m * m;
    float rs = rsqrtf(v + BN_EPS) * g[c];
    scale[c] = rs;
    shift[c] = be[c] - m * rs;
}

__global__ void pnorm_k(const float* __restrict__ p, float* __restrict__ pn) {
    int t = threadIdx.x;
    float v = p[t];
    float s = v * v;
    #pragma unroll
    for (int o = 16; o > 0; o >>= 1) s += __shfl_down_sync(0xffffffff, s, o);
    __shared__ float red[32];
    if ((t & 31) == 0) red[t >> 5] = s;
    __syncthreads();
    if (t < 32) {
        float x = red[t];
        #pragma unroll
        for (int o = 16; o > 0; o >>= 1) x += __shfl_down_sync(0xffffffff, x, o);
        if (t == 0) red[0] = x;
    }
    __syncthreads();
    pn[t] = v * rsqrtf(red[0]);
}

__global__ void score_k(const float* __restrict__ X, const float* __restrict__ scale,
                        const float* __restrict__ shift, const float* __restrict__ pn,
                        float* __restrict__ score) {
    int row = blockIdx.x, t = threadIdx.x;
    size_t base = (size_t)row * HD + t * 4;
    float4 v = *(const float4*)&X[base];
    float4 sc = *(const float4*)&scale[t * 4];
    float4 sh = *(const float4*)&shift[t * 4];
    v.x = fmaxf(fmaf(v.x, sc.x, sh.x), 0.f);
    v.y = fmaxf(fmaf(v.y, sc.y, sh.y), 0.f);
    v.z = fmaxf(fmaf(v.z, sc.z, sh.z), 0.f);
    v.w = fmaxf(fmaf(v.w, sc.w, sh.w), 0.f);
    float4 p = *(const float4*)&pn[t * 4];
    float dot = v.x * p.x + v.y * p.y + v.z * p.z + v.w * p.w;
    #pragma unroll
    for (int o = 16; o > 0; o >>= 1) dot += __shfl_down_sync(0xffffffff, dot, o);
    __shared__ float red[8];
    if ((t & 31) == 0) red[t >> 5] = dot;
    __syncthreads();
    if (t == 0) {
        float s = 0.f;
        #pragma unroll
        for (int i = 0; i < 8; i++) s += red[i];
        score[row] = tanhf(s);
    }
}

template<int NPGT, int KK>
__global__ void topk_k(const float* __restrict__ score, float* __restrict__ val,
                       int* __restrict__ perm, int* __restrict__ newid) {
    __shared__ float s[NPGT];
    __shared__ int   id[NPGT];
    int b = blockIdx.x, t = threadIdx.x;
    s[t] = score[b * NPGT + t];
    id[t] = t;
    for (int size = 2; size <= NPGT; size <<= 1) {
        for (int stride = size >> 1; stride > 0; stride >>= 1) {
            __syncthreads();
            int j = t ^ stride;
            if (j > t) {
                float a = s[t], c = s[j];
                int ia = id[t], ic = id[j];
                bool aFirst = (a > c) || (a == c && ia < ic);
                bool descHere = ((t & size) == 0);
                if (descHere ? !aFirst : aFirst) {
                    s[t] = c; s[j] = a; id[t] = ic; id[j] = ia;
                }
            }
        }
    }
    __syncthreads();
    if (t < KK) {
        perm[b * KK + t] = b * NPGT + id[t];
        val[b * KK + t] = s[t];
        if (newid) newid[b * NPGT + id[t]] = b * KK + t;
    } else if (newid) {
        newid[b * NPGT + id[t]] = -1;
    }
}

// lazy BN+ReLU gather: hp[row] = relu(agg[perm]*sc+sh) * val
__global__ void gather_bn_k(const float* __restrict__ Hin, const int* __restrict__ perm,
                            const float* __restrict__ val,
                            const float* __restrict__ scale, const float* __restrict__ shift,
                            float* __restrict__ Hout) {
    int row = blockIdx.x, t = threadIdx.x;
    int srow = perm[row];
    float v = val[row];
    float4 x = *(const float4*)&Hin[(size_t)srow * HD + t * 4];
    float4 sc = *(const float4*)&scale[t * 4];
    float4 sh = *(const float4*)&shift[t * 4];
    x.x = fmaxf(fmaf(x.x, sc.x, sh.x), 0.f) * v;
    x.y = fmaxf(fmaf(x.y, sc.y, sh.y), 0.f) * v;
    x.z = fmaxf(fmaf(x.z, sc.z, sh.z), 0.f) * v;
    x.w = fmaxf(fmaf(x.w, sc.w, sh.w), 0.f) * v;
    *(float4*)&Hout[(size_t)row * HD + t * 4] = x;
}

__global__ void meanpool_k(const float* __restrict__ Hin, float* __restrict__ out, int kpg) {
    int b = blockIdx.x;
    int c = blockIdx.y * 256 + threadIdx.x;
    float sum = 0.f;
    const float* p = Hin + (size_t)b * kpg * HD + c;
    for (int r = 0; r < kpg; r++) sum += p[(size_t)r * HD];
    out[b * HD + c] = sum / (float)kpg;
}

// fused layer-2 gather_bn + meanpool
__global__ void gpool2_k(const float* __restrict__ agg2, const int* __restrict__ perm,
                         const float* __restrict__ val,
                         const float* __restrict__ scale, const float* __restrict__ shift,
                         float* __restrict__ x2out) {
    int b = blockIdx.x;
    int c = blockIdx.y * 256 + threadIdx.x;
    float sc = scale[c], sh = shift[c];
    float sum = 0.f;
    #pragma unroll 4
    for (int r = 0; r < KP2; r++) {
        int srow = __ldg(&perm[b * KP2 + r]);
        float v = __ldg(&val[b * KP2 + r]);
        float xx = __ldg(&agg2[(size_t)srow * HD + c]);
        sum += fmaxf(fmaf(xx, sc, sh), 0.f) * v;
    }
    x2out[b * HD + c] = sum * (1.0f / (float)KP2);
}

// fused head: z = relu((x1+x2)@Wf + bf) ; out = z@Wf1 + bf1  (one block per graph)
__global__ void fchead_k(const float* __restrict__ x1, const float* __restrict__ x2,
                         const float* __restrict__ Wf, const float* __restrict__ bf,
                         const float* __restrict__ Wf1, const float* __restrict__ bf1,
                         float* __restrict__ out) {
    __shared__ float xs[HD];
    __shared__ float zs[FC1D];
    int m = blockIdx.x, c = threadIdx.x;
    xs[c]       = x1[m * HD + c]       + x2[m * HD + c];
    xs[c + 512] = x1[m * HD + c + 512] + x2[m * HD + c + 512];
    __syncthreads();
    float s = bf[c];
    #pragma unroll 4
    for (int k = 0; k < HD; k++) s += xs[k] * Wf[(size_t)k * FC1D + c];
    zs[c] = fmaxf(s, 0.f);
    __syncthreads();
    if (c < OUTD) {
        float o = bf1[c];
        #pragma unroll 4
        for (int k = 0; k < FC1D; k++) o += zs[k] * Wf1[k * OUTD + c];
        out[m * OUTD + c] = o;
    }
}

// ---------------- launch ----------------
extern "C" void kernel_launch(void* const* d_in, const int* in_sizes, int n_in,
                              void* d_out, int out_size) {
    (void)in_sizes; (void)n_in; (void)out_size;
    float* FS = nullptr; int* IS = nullptr;
    __nv_bfloat16 *a1s = nullptr, *w1s = nullptr, *a2s = nullptr, *w2s = nullptr;
    cudaGetSymbolAddress((void**)&FS, d_fscratch);
    cudaGetSymbolAddress((void**)&IS, d_iscratch);
    cudaGetSymbolAddress((void**)&a1s, d_a1s);
    cudaGetSymbolAddress((void**)&w1s, d_w1s);
    cudaGetSymbolAddress((void**)&a2s, d_a2s);
    cudaGetSymbolAddress((void**)&w2s, d_w2s);
    cudaFuncSetAttribute(gemm_mma, cudaFuncAttributeMaxDynamicSharedMemorySize, GEMM_SMEM_DYN);

    static cudaStream_t sB = nullptr;
    static cudaEvent_t eF = nullptr, eB1 = nullptr, eT1 = nullptr, eG1 = nullptr,
                       eB2 = nullptr, eMP = nullptr;
    if (!sB) {
        cudaStreamCreateWithFlags(&sB, cudaStreamNonBlocking);
        cudaEventCreateWithFlags(&eF,  cudaEventDisableTiming);
        cudaEventCreateWithFlags(&eB1, cudaEventDisableTiming);
        cudaEventCreateWithFlags(&eT1, cudaEventDisableTiming);
        cudaEventCreateWithFlags(&eG1, cudaEventDisableTiming);
        cudaEventCreateWithFlags(&eB2, cudaEventDisableTiming);
        cudaEventCreateWithFlags(&eMP, cudaEventDisableTiming);
    }

    const float* x   = (const float*)d_in[0];
    const int*   ei  = (const int*)d_in[1];
    const float* W1  = (const float*)d_in[3];
    const float* g1  = (const float*)d_in[5];
    const float* be1 = (const float*)d_in[6];
    const float* p1  = (const float*)d_in[7];
    const float* W2  = (const float*)d_in[8];
    const float* g2  = (const float*)d_in[10];
    const float* be2 = (const float*)d_in[11];
    const float* p2  = (const float*)d_in[12];
    const float* Wf  = (const float*)d_in[13];
    const float* bf  = (const float*)d_in[14];
    const float* Wf1 = (const float*)d_in[15];
    const float* bf1 = (const float*)d_in[16];
    float* out = (float*)d_out;

    const int* src = ei;
    const int* dst = ei + E_TOT;

    float* agg1  = FS + F_AGG1;
    float* hp1   = FS + F_HP1;
    float* agg2  = FS + F_AGG2;
    float* dinv1 = FS + F_DINV1;
    float* dinv2 = FS + F_DINV2;
    float* score1= FS + F_SCORE1;
    float* score2= FS + F_SCORE2;
    float* val1  = FS + F_VAL1;
    float* val2  = FS + F_VAL2;
    float* cols  = FS + F_COLS;
    float* csum1 = cols, *csq1 = cols + HD, *csum2 = cols + 2 * HD, *csq2 = cols + 3 * HD;
    float* scale = FS + F_SCALE;
    float* shift = FS + F_SHIFT;
    float* pn1   = FS + F_PN1;
    float* pn2   = FS + F_PN2;
    float* x1    = FS + F_X1;
    float* x2    = FS + F_X2;

    int* src2  = IS + I_SRC2;
    int* dst2  = IS + I_DST2;
    int* csr   = IS + I_CSR;
    int* cnt1  = IS + I_CNT1;
    int* cnt2  = IS + I_CNT2;
    int* off1  = IS + I_OFF1;
    int* cur1  = IS + I_CUR1;
    int* off2  = IS + I_OFF2;
    int* cur2  = IS + I_CUR2;
    int* perm1 = IS + I_PERM1;
    int* perm2 = IS + I_PERM2;
    int* newid = IS + I_NEWID;

    // ===== fork: side stream does weight splits + pnorms + colsum zero =====
    cudaEventRecord(eF, 0);
    cudaStreamWaitEvent(sB, eF, 0);
    wsplit_k<<<(F_IN * HD) / 256, 256, 0, sB>>>(W1, w1s, F_IN);
    wsplit_k<<<(HD * HD) / 256, 256, 0, sB>>>(W2, w2s, HD);
    fill_k<<<(4 * HD) / 256, 256, 0, sB>>>(cols, 4 * HD, 0.f);
    pnorm_k<<<1, HD, 0, sB>>>(p1, pn1);
    pnorm_k<<<1, HD, 0, sB>>>(p2, pn2);
    cudaEventRecord(eB1, sB);

    // ===== main: CSR1 -> gather+split(X) -> GEMM1 (direct agg1 + stats) =====
    zero_int_k<<<(N1 + N2 + 255) / 256, 256>>>(cnt1, N1 + N2);
    count_k<<<E_TOT / 256, 256>>>(dst, cnt1, E_TOT);
    scan_off_k<NPG><<<BG, NPG>>>(cnt1, off1, cur1, dinv1);
    fill_csr_k<<<E_TOT / 256, 256>>>(src, dst, cur1, csr, E_TOT, 0);
    gxsplit_k<<<N1, 128>>>(x, csr, off1, cnt1, dinv1, a1s);
    cudaStreamWaitEvent(0, eB1, 0);
    gemm_mma<<<dim3(HD / 128, N1 / 128), 256, GEMM_SMEM_DYN>>>(
        a1s, w1s, agg1, 3 * F_IN, 2 * F_IN, csum1, csq1);

    bnprep_k<<<HD / 256, 256>>>(csum1, csq1, 1.0f / (float)N1, g1, be1, scale, shift);
    score_k<<<N1, 256>>>(agg1, scale, shift, pn1, score1);
    topk_k<NPG, KP1><<<BG, NPG>>>(score1, val1, perm1, newid);
    cudaEventRecord(eT1, 0);

    // side: CSR for layer 2 (overlaps main's gather_bn)
    cudaStreamWaitEvent(sB, eT1, 0);
    remapcount_k<<<E_TOT / 256, 256, 0, sB>>>(src, dst, newid, src2, dst2, cnt2, E_TOT);
    scan_off_k<KP1><<<BG, KP1, 0, sB>>>(cnt2, off2, cur2, dinv2);
    fill_csr_k<<<E_TOT / 256, 256, 0, sB>>>(src2, dst2, cur2, csr, E_TOT, 1);
    cudaEventRecord(eB2, sB);

    gather_bn_k<<<N2, 256>>>(agg1, perm1, val1, scale, shift, hp1);
    cudaEventRecord(eG1, 0);
    // meanpool1 on side stream
    cudaStreamWaitEvent(sB, eG1, 0);
    meanpool_k<<<dim3(BG, HD / 256), 256, 0, sB>>>(hp1, x1, KP1);
    cudaEventRecord(eMP, sB);

    // ===== layer 2: gather(hp1)+split -> GEMM2 (direct agg2 + stats) =====
    cudaStreamWaitEvent(0, eB2, 0);
    y2split_k<<<N2, 256>>>(hp1, csr, off2, cnt2, dinv2, a2s);
    gemm_mma<<<dim3(HD / 128, N2 / 128), 256, GEMM_SMEM_DYN>>>(
        a2s, w2s, agg2, 3 * HD, 2 * HD, csum2, csq2);

    bnprep_k<<<HD / 256, 256>>>(csum2, csq2, 1.0f / (float)N2, g2, be2, scale, shift);
    score_k<<<N2, 256>>>(agg2, scale, shift, pn2, score2);
    topk_k<KP1, KP2><<<BG, KP1>>>(score2, val2, perm2, nullptr);
    gpool2_k<<<dim3(BG, HD / 256), 256>>>(agg2, perm2, val2, scale, shift, x2);

    // ===== Head (fused) =====
    cudaStreamWaitEvent(0, eMP, 0);
    fchead_k<<<BG, FC1D>>>(x1, x2, Wf, bf, Wf1, bf1, out);
}

// round 14
// speedup vs baseline: 1.0778x; 1.0368x over previous
#include <cuda_runtime.h>
#include <cuda_bf16.h>
#include <math.h>
#include <cstdint>

// ---------------- problem constants ----------------
#define BG     32
#define NPG    1024
#define DEGC   8
#define F_IN   512
#define HD     1024
#define OUTD   10
#define E_TOT  (BG*NPG*DEGC)   // 262144
#define EPG    (NPG*DEGC)      // 8192
#define N1     (BG*NPG)        // 32768
#define KP1    512
#define N2     (BG*KP1)        // 16384
#define KP2    256
#define N3     (BG*KP2)        // 8192
#define FC1D   512
#define BN_EPS 1e-5f

// ---------------- scratch layout (floats) ----------------
#define F_AGG1    ((size_t)0)
#define F_HP1     (F_AGG1 + (size_t)N1*HD)
#define F_AGG2    (F_HP1  + (size_t)N2*HD)
#define F_DINV1   (F_AGG2 + (size_t)N2*HD)
#define F_DINV2   (F_DINV1 + N1)
#define F_SCORE1  (F_DINV2 + N2)
#define F_SCORE2  (F_SCORE1 + N1)
#define F_VAL1    (F_SCORE2 + N2)
#define F_VAL2    (F_VAL1 + N2)
#define F_COLS    (F_VAL2 + N3)          // csum1,csq1,csum2,csq2 : 4*HD
#define F_SCALE   (F_COLS + 4*HD)
#define F_SHIFT   (F_SCALE + HD)
#define F_PN1     (F_SHIFT + HD)
#define F_PN2     (F_PN1 + HD)
#define F_X1      (F_PN2 + HD)
#define F_X2      (F_X1 + BG*HD)
#define F_END     (F_X2 + BG*HD)

#define I_SRC2   ((size_t)0)
#define I_DST2   (I_SRC2 + E_TOT)
#define I_CSR    (I_DST2 + E_TOT)
#define I_CNT1   (I_CSR + E_TOT)
#define I_CNT2   (I_CNT1 + N1)
#define I_OFF1   (I_CNT2 + N2)
#define I_CUR1   (I_OFF1 + N1)
#define I_OFF2   (I_CUR1 + N1)
#define I_CUR2   (I_OFF2 + N2)
#define I_PERM1  (I_CUR2 + N2)
#define I_PERM2  (I_PERM1 + N2)
#define I_NEWID  (I_PERM2 + N3)
#define I_END    (I_NEWID + N1)

__device__ float d_fscratch[F_END];
__device__ int   d_iscratch[I_END];

// A stored [hi|lo] (2K wide); B stored [hi|lo|hi] (3K wide)
__device__ __nv_bfloat16 d_a1s[(size_t)N1 * 2 * F_IN];
__device__ __nv_bfloat16 d_w1s[(size_t)HD * 3 * F_IN];
__device__ __nv_bfloat16 d_a2s[(size_t)N2 * 2 * HD];
__device__ __nv_bfloat16 d_w2s[(size_t)HD * 3 * HD];

// ================= helpers =================
__device__ __forceinline__ uint32_t smem_u32(const void* p) {
    uint32_t a;
    asm("{ .reg .u64 t; cvta.to.shared.u64 t, %1; cvt.u32.u64 %0, t; }" : "=r"(a) : "l"(p));
    return a;
}
#define SWZ128(b) ((b) ^ (((b) >> 3) & 0x70))

__device__ __forceinline__ void cp16(uint32_t dst, const void* src) {
    asm volatile("cp.async.cg.shared.global [%0], [%1], 16;" :: "r"(dst), "l"(src));
}

#define LDSM4(r0, r1, r2, r3, addr) \
    asm volatile("ldmatrix.sync.aligned.m8n8.x4.shared.b16 {%0,%1,%2,%3}, [%4];" \
                 : "=r"(r0), "=r"(r1), "=r"(r2), "=r"(r3) : "r"(addr))

#define MMA16816(d, a, b0, b1) \
    asm volatile("mma.sync.aligned.m16n8k16.row.col.f32.bf16.bf16.f32 " \
                 "{%0,%1,%2,%3}, {%4,%5,%6,%7}, {%8,%9}, {%0,%1,%2,%3};" \
                 : "+f"((d)[0]), "+f"((d)[1]), "+f"((d)[2]), "+f"((d)[3]) \
                 : "r"((a)[0]), "r"((a)[1]), "r"((a)[2]), "r"((a)[3]), \
                   "r"(b0), "r"(b1))

#define GEMM_SMEM_DYN (3 * 32768 + 1024)

// ---- HMMA GEMM, 128 threads (4 warps x 64x64 warp tile), fused column stats.
// A is [hi|lo] (stride KA), K-schedule hi,hi,lo. 3-stage ring, 2 CTAs/SM.
__global__ void __launch_bounds__(128, 2) gemm_mma(
    const __nv_bfloat16* __restrict__ A, const __nv_bfloat16* __restrict__ B,
    float* __restrict__ C, int K3, int KA,
    float* __restrict__ csum, float* __restrict__ csq)
{
    extern __shared__ char smem[];
    const uint32_t base = (smem_u32(smem) + 1023u) & ~1023u;
    const int tid = threadIdx.x, wid = tid >> 5, lane = tid & 31;
    const int m0 = blockIdx.y * 128;
    const int n0 = blockIdx.x * 128;
    const int wm = (wid & 1) * 64;      // warp rows base (64 rows per warp)
    const int wn = (wid >> 1) * 64;     // warp cols base (64 cols per warp)

    float acc[4][8][4];
    #pragma unroll
    for (int i = 0; i < 4; i++)
        #pragma unroll
        for (int j = 0; j < 8; j++)
            #pragma unroll
            for (int r = 0; r < 4; r++) acc[i][j][r] = 0.f;

    const int rA0 = (wm + (lane & 15)) * 128;
    const int cA  = (lane >> 4) * 16;
    const int rBb = (wn + ((lane >> 4) << 3) + (lane & 7)) * 128;
    const int cB  = ((lane >> 3) & 1) * 16;

    const int nStages = K3 >> 6;
    const int third = nStages / 3;
    const __nv_bfloat16* Abase = A + (size_t)m0 * KA;
    const __nv_bfloat16* Bbase = B + (size_t)n0 * K3;
    const int lrow = tid >> 3, lc8 = tid & 7;    // 16 rows x 8 col-chunks per i-step

    #pragma unroll
    for (int s = 0; s < 2; s++) {
        uint32_t dA = base + s * 32768, dB = dA + 16384;
        int ac = (s >= third) ? s - third : s;
        const __nv_bfloat16* Ab = Abase + ac * 64;
        const __nv_bfloat16* Bb = Bbase + s * 64;
        #pragma unroll
        for (int i = 0; i < 8; i++) {
            int row = lrow + i * 16;
            cp16(dA + SWZ128(row * 128 + lc8 * 16), Ab + (size_t)row * KA + lc8 * 8);
            cp16(dB + SWZ128(row * 128 + lc8 * 16), Bb + (size_t)row * K3 + lc8 * 8);
        }
        asm volatile("cp.async.commit_group;" ::: "memory");
    }

    int buf = 0, pbuf = 2;
    for (int ks = 0; ks < nStages; ks++) {
        asm volatile("cp.async.wait_group 1;" ::: "memory");
        __syncthreads();

        if (ks + 2 < nStages) {
            uint32_t dA = base + pbuf * 32768, dB = dA + 16384;
            int c = ks + 2;
            int ac = (c >= third) ? c - third : c;
            const __nv_bfloat16* Ab = Abase + ac * 64;
            const __nv_bfloat16* Bb = Bbase + c * 64;
            #pragma unroll
            for (int i = 0; i < 8; i++) {
                int row = lrow + i * 16;
                cp16(dA + SWZ128(row * 128 + lc8 * 16), Ab + (size_t)row * KA + lc8 * 8);
                cp16(dB + SWZ128(row * 128 + lc8 * 16), Bb + (size_t)row * K3 + lc8 * 8);
            }
        }
        asm volatile("cp.async.commit_group;" ::: "memory");

        const uint32_t As = base + buf * 32768;
        const uint32_t Bs = As + 16384;
        #pragma unroll
        for (int kk = 0; kk < 4; kk++) {
            const int kb = kk * 32;
            uint32_t af[4][4];
            #pragma unroll
            for (int mi = 0; mi < 4; mi++)
                LDSM4(af[mi][0], af[mi][1], af[mi][2], af[mi][3],
                      As + SWZ128(rA0 + mi * 16 * 128 + cA + kb));
            uint32_t bf[4][4];
            #pragma unroll
            for (int jj = 0; jj < 4; jj++)
                LDSM4(bf[jj][0], bf[jj][1], bf[jj][2], bf[jj][3],
                      Bs + SWZ128(rBb + jj * 16 * 128 + cB + kb));
            #pragma unroll
            for (int j = 0; j < 8; j++) {
                const int jj = j >> 1, hh = (j & 1) * 2;
                #pragma unroll
                for (int mi = 0; mi < 4; mi++)
                    MMA16816(acc[mi][j], af[mi], bf[jj][hh], bf[jj][hh + 1]);
            }
        }
        buf = (buf == 2) ? 0 : buf + 1;
        pbuf = (pbuf == 2) ? 0 : pbuf + 1;
    }

    const int rq = lane >> 2, cq = (lane & 3) * 2;
    #pragma unroll
    for (int mi = 0; mi < 4; mi++) {
        int rowb = m0 + wm + mi * 16 + rq;
        #pragma unroll
        for (int j = 0; j < 8; j++) {
            float* p0 = C + (size_t)rowb * HD + n0 + wn + j * 8 + cq;
            *(float2*)p0 = make_float2(acc[mi][j][0], acc[mi][j][1]);
            *(float2*)(p0 + 8 * (size_t)HD) = make_float2(acc[mi][j][2], acc[mi][j][3]);
        }
    }

    // fused column stats (per warp: 64 rows per column)
    #pragma unroll
    for (int j = 0; j < 8; j++) {
        float s0 = 0.f, s1 = 0.f, q0 = 0.f, q1 = 0.f;
        #pragma unroll
        for (int mi = 0; mi < 4; mi++) {
            s0 += acc[mi][j][0] + acc[mi][j][2];
            s1 += acc[mi][j][1] + acc[mi][j][3];
            q0 += acc[mi][j][0] * acc[mi][j][0] + acc[mi][j][2] * acc[mi][j][2];
            q1 += acc[mi][j][1] * acc[mi][j][1] + acc[mi][j][3] * acc[mi][j][3];
        }
        #pragma unroll
        for (int o = 16; o >= 4; o >>= 1) {
            s0 += __shfl_down_sync(0xffffffff, s0, o);
            s1 += __shfl_down_sync(0xffffffff, s1, o);
            q0 += __shfl_down_sync(0xffffffff, q0, o);
            q1 += __shfl_down_sync(0xffffffff, q1, o);
        }
        if (lane < 4) {
            int col = n0 + wn + j * 8 + lane * 2;
            atomicAdd(&csum[col], s0);
            atomicAdd(&csum[col + 1], s1);
            atomicAdd(&csq[col], q0);
            atomicAdd(&csq[col + 1], q1);
        }
    }
}

// ---- weight split (B' = [hi|lo|hi], 3K) ----
__global__ void wsplit_k(const float* __restrict__ W, __nv_bfloat16* __restrict__ O, int K) {
    int i = blockIdx.x * blockDim.x + threadIdx.x;
    int k = i >> 10, n = i & 1023;
    if (k >= K) return;
    float v = W[i];
    __nv_bfloat16 hi = __float2bfloat16(v);
    __nv_bfloat16 lo = __float2bfloat16(v - __bfloat162float(hi));
    size_t base = (size_t)n * (3 * K);
    O[base + k] = hi; O[base + K + k] = lo; O[base + 2 * K + k] = hi;
}

// ---------------- CSR build ----------------
__global__ void zero_int_k(int* p, int n) {
    int i = blockIdx.x * blockDim.x + threadIdx.x;
    if (i < n) p[i] = 0;
}

__global__ void count_k(const int* __restrict__ dstv, int* __restrict__ cnt, int n) {
    int e = blockIdx.x * blockDim.x + threadIdx.x;
    if (e < n) atomicAdd(&cnt[dstv[e]], 1);
}

__global__ void remapcount_k(const int* __restrict__ src, const int* __restrict__ dst,
                             const int* __restrict__ newid, int* __restrict__ src2,
                             int* __restrict__ dst2, int* __restrict__ cnt2, int n) {
    int e = blockIdx.x * blockDim.x + threadIdx.x;
    if (e >= n) return;
    int s = newid[src[e]], d = newid[dst[e]];
    if (s < 0 || d < 0) { src2[e] = -1; dst2[e] = 0; }
    else { src2[e] = s; dst2[e] = d; atomicAdd(&cnt2[d], 1); }
}

template<int NPGT>
__global__ void scan_off_k(const int* __restrict__ cnt, int* __restrict__ off,
                           int* __restrict__ cursor, float* __restrict__ dinv) {
    __shared__ int sh[NPGT];
    int b = blockIdx.x, t = threadIdx.x;
    int v = cnt[b * NPGT + t];
    sh[t] = v;
    dinv[b * NPGT + t] = rsqrtf(1.0f + (float)v);
    __syncthreads();
    #pragma unroll
    for (int d = 1; d < NPGT; d <<= 1) {
        int add = (t >= d) ? sh[t - d] : 0;
        __syncthreads();
        sh[t] += add;
        __syncthreads();
    }
    int o = b * EPG + sh[t] - v;
    off[b * NPGT + t] = o;
    cursor[b * NPGT + t] = o;
}

__global__ void fill_csr_k(const int* __restrict__ srcv, const int* __restrict__ dstv,
                           int* __restrict__ cursor, int* __restrict__ csr, int n, int checkValid) {
    int e = blockIdx.x * blockDim.x + threadIdx.x;
    if (e >= n) return;
    int s = srcv[e];
    if (checkValid && s < 0) return;
    int pos = atomicAdd(&cursor[dstv[e]], 1);
    csr[pos] = s;
}

// ---- layer-1 gather over X with fused bf16 [hi|lo] split output
__global__ void __launch_bounds__(128) gxsplit_k(
    const float* __restrict__ X, const int* __restrict__ csr,
    const int* __restrict__ off, const int* __restrict__ cnt,
    const float* __restrict__ dinv, __nv_bfloat16* __restrict__ As)
{
    const int n = blockIdx.x, t = threadIdx.x;
    const float iv = dinv[n];
    const int o = off[n], c = cnt[n];
    float4 l = ((const float4*)(X + (size_t)n * F_IN))[t];
    const float iv2 = iv * iv;
    float4 acc = make_float4(l.x * iv2, l.y * iv2, l.z * iv2, l.w * iv2);
    int j = 0;
    for (; j + 1 < c; j += 2) {
        int s0 = __ldg(&csr[o + j]), s1 = __ldg(&csr[o + j + 1]);
        float w0 = __ldg(&dinv[s0]) * iv, w1 = __ldg(&dinv[s1]) * iv;
        float4 v0 = ((const float4*)(X + (size_t)s0 * F_IN))[t];
        float4 v1 = ((const float4*)(X + (size_t)s1 * F_IN))[t];
        acc.x += v0.x * w0 + v1.x * w1;
        acc.y += v0.y * w0 + v1.y * w1;
        acc.z += v0.z * w0 + v1.z * w1;
        acc.w += v0.w * w0 + v1.w * w1;
    }
    if (j < c) {
        int s0 = __ldg(&csr[o + j]);
        float w0 = __ldg(&dinv[s0]) * iv;
        float4 v0 = ((const float4*)(X + (size_t)s0 * F_IN))[t];
        acc.x += v0.x * w0; acc.y += v0.y * w0;
        acc.z += v0.z * w0; acc.w += v0.w * w0;
    }
    __nv_bfloat16* rp = As + (size_t)n * (2 * F_IN);
    int k = t * 4;
    float vs[4] = {acc.x, acc.y, acc.z, acc.w};
    #pragma unroll
    for (int i = 0; i < 4; i++) {
        __nv_bfloat16 h = __float2bfloat16(vs[i]);
        rp[k + i] = h;
        rp[F_IN + k + i] = __float2bfloat16(vs[i] - __bfloat162float(h));
    }
}

// ---- layer-2 gather over hp1 with fused bf16 [hi|lo] split output
__global__ void __launch_bounds__(256) y2split_k(
    const float* __restrict__ H, const int* __restrict__ csr,
    const int* __restrict__ off, const int* __restrict__ cnt,
    const float* __restrict__ dinv, __nv_bfloat16* __restrict__ As)
{
    const int n = blockIdx.x, t = threadIdx.x;
    const float iv = dinv[n];
    const int o = off[n], c = cnt[n];
    float4 l = ((const float4*)(H + (size_t)n * HD))[t];
    const float iv2 = iv * iv;
    float4 acc = make_float4(l.x * iv2, l.y * iv2, l.z * iv2, l.w * iv2);
    int j = 0;
    for (; j + 1 < c; j += 2) {
        int s0 = __ldg(&csr[o + j]), s1 = __ldg(&csr[o + j + 1]);
        float w0 = __ldg(&dinv[s0]) * iv, w1 = __ldg(&dinv[s1]) * iv;
        float4 v0 = ((const float4*)(H + (size_t)s0 * HD))[t];
        float4 v1 = ((const float4*)(H + (size_t)s1 * HD))[t];
        acc.x += v0.x * w0 + v1.x * w1;
        acc.y += v0.y * w0 + v1.y * w1;
        acc.z += v0.z * w0 + v1.z * w1;
        acc.w += v0.w * w0 + v1.w * w1;
    }
    if (j < c) {
        int s0 = __ldg(&csr[o + j]);
        float w0 = __ldg(&dinv[s0]) * iv;
        float4 v0 = ((const float4*)(H + (size_t)s0 * HD))[t];
        acc.x += v0.x * w0; acc.y += v0.y * w0;
        acc.z += v0.z * w0; acc.w += v0.w * w0;
    }
    __nv_bfloat16* rp = As + (size_t)n * (2 * HD);
    int k = t * 4;
    float vs[4] = {acc.x, acc.y, acc.z, acc.w};
    #pragma unroll
    for (int i = 0; i < 4; i++) {
        __nv_bfloat16 h = __float2bfloat16(vs[i]);
        rp[k + i] = h;
        rp[HD + k + i] = __float2bfloat16(vs[i] - __bfloat162float(h));
    }
}

// ---------------- BN / score / pooling ----------------
__global__ void fill_k(float* p, int n, float v) {
    int i = blockIdx.x * blockDim.x + threadIdx.x;
    if (i < n) p[i] = v;
}

__global__ void bnprep_k(const float* __restrict__ csum, const float* __restrict__ csq,
                         float invn, const float* __restrict__ g, const float* __restrict__ be,
                         float* __restrict__ scale, float* __restrict__ shift) {
    int c = blockIdx.x * blockDim.x + threadIdx.x;
    float m = csum[c] * invn;
    float v = csq[c] * invn - m * m;
    float rs = rsqrtf(v + BN_EPS) * g[c];
    scale[c] = rs;
    shift[c] = be[c] - m * rs;
}

__global__ void pnorm_k(const float* __restrict__ p, float* __restrict__ pn) {
    int t = threadIdx.x;
    float v = p[t];
    float s = v * v;
    #pragma unroll
    for (int o = 16; o > 0; o >>= 1) s += __shfl_down_sync(0xffffffff, s, o);
    __shared__ float red[32];
    if ((t & 31) == 0) red[t >> 5] = s;
    __syncthreads();
    if (t < 32) {
        float x = red[t];
        #pragma unroll
        for (int o = 16; o > 0; o >>= 1) x += __shfl_down_sync(0xffffffff, x, o);
        if (t == 0) red[0] = x;
    }
    __syncthreads();
    pn[t] = v * rsqrtf(red[0]);
}

__global__ void score_k(const float* __restrict__ X, const float* __restrict__ scale,
                        const float* __restrict__ shift, const float* __restrict__ pn,
                        float* __restrict__ score) {
    int row = blockIdx.x, t = threadIdx.x;
    size_t base = (size_t)row * HD + t * 4;
    float4 v = *(const float4*)&X[base];
    float4 sc = *(const float4*)&scale[t * 4];
    float4 sh = *(const float4*)&shift[t * 4];
    v.x = fmaxf(fmaf(v.x, sc.x, sh.x), 0.f);
    v.y = fmaxf(fmaf(v.y, sc.y, sh.y), 0.f);
    v.z = fmaxf(fmaf(v.z, sc.z, sh.z), 0.f);
    v.w = fmaxf(fmaf(v.w, sc.w, sh.w), 0.f);
    float4 p = *(const float4*)&pn[t * 4];
    float dot = v.x * p.x + v.y * p.y + v.z * p.z + v.w * p.w;
    #pragma unroll
    for (int o = 16; o > 0; o >>= 1) dot += __shfl_down_sync(0xffffffff, dot, o);
    __shared__ float red[8];
    if ((t & 31) == 0) red[t >> 5] = dot;
    __syncthreads();
    if (t == 0) {
        float s = 0.f;
        #pragma unroll
        for (int i = 0; i < 8; i++) s += red[i];
        score[row] = tanhf(s);
    }
}

template<int NPGT, int KK>
__global__ void topk_k(const float* __restrict__ score, float* __restrict__ val,
                       int* __restrict__ perm, int* __restrict__ newid) {
    __shared__ float s[NPGT];
    __shared__ int   id[NPGT];
    int b = blockIdx.x, t = threadIdx.x;
    s[t] = score[b * NPGT + t];
    id[t] = t;
    for (int size = 2; size <= NPGT; size <<= 1) {
        for (int stride = size >> 1; stride > 0; stride >>= 1) {
            __syncthreads();
            int j = t ^ stride;
            if (j > t) {
                float a = s[t], c = s[j];
                int ia = id[t], ic = id[j];
                bool aFirst = (a > c) || (a == c && ia < ic);
                bool descHere = ((t & size) == 0);
                if (descHere ? !aFirst : aFirst) {
                    s[t] = c; s[j] = a; id[t] = ic; id[j] = ia;
                }
            }
        }
    }
    __syncthreads();
    if (t < KK) {
        perm[b * KK + t] = b * NPGT + id[t];
        val[b * KK + t] = s[t];
        if (newid) newid[b * NPGT + id[t]] = b * KK + t;
    } else if (newid) {
        newid[b * NPGT + id[t]] = -1;
    }
}

// lazy BN+ReLU gather: hp[row] = relu(agg[perm]*sc+sh) * val
__global__ void gather_bn_k(const float* __restrict__ Hin, const int* __restrict__ perm,
                            const float* __restrict__ val,
                            const float* __restrict__ scale, const float* __restrict__ shift,
                            float* __restrict__ Hout) {
    int row = blockIdx.x, t = threadIdx.x;
    int srow = perm[row];
    float v = val[row];
    float4 x = *(const float4*)&Hin[(size_t)srow * HD + t * 4];
    float4 sc = *(const float4*)&scale[t * 4];
    float4 sh = *(const float4*)&shift[t * 4];
    x.x = fmaxf(fmaf(x.x, sc.x, sh.x), 0.f) * v;
    x.y = fmaxf(fmaf(x.y, sc.y, sh.y), 0.f) * v;
    x.z = fmaxf(fmaf(x.z, sc.z, sh.z), 0.f) * v;
    x.w = fmaxf(fmaf(x.w, sc.w, sh.w), 0.f) * v;
    *(float4*)&Hout[(size_t)row * HD + t * 4] = x;
}

__global__ void meanpool_k(const float* __restrict__ Hin, float* __restrict__ out, int kpg) {
    int b = blockIdx.x;
    int c = blockIdx.y * 256 + threadIdx.x;
    float sum = 0.f;
    const float* p = Hin + (size_t)b * kpg * HD + c;
    for (int r = 0; r < kpg; r++) sum += p[(size_t)r * HD];
    out[b * HD + c] = sum / (float)kpg;
}

// fused layer-2 gather_bn + meanpool
__global__ void gpool2_k(const float* __restrict__ agg2, const int* __restrict__ perm,
                         const float* __restrict__ val,
                         const float* __restrict__ scale, const float* __restrict__ shift,
                         float* __restrict__ x2out) {
    int b = blockIdx.x;
    int c = blockIdx.y * 256 + threadIdx.x;
    float sc = scale[c], sh = shift[c];
    float sum = 0.f;
    #pragma unroll 4
    for (int r = 0; r < KP2; r++) {
        int srow = __ldg(&perm[b * KP2 + r]);
        float v = __ldg(&val[b * KP2 + r]);
        float xx = __ldg(&agg2[(size_t)srow * HD + c]);
        sum += fmaxf(fmaf(xx, sc, sh), 0.f) * v;
    }
    x2out[b * HD + c] = sum * (1.0f / (float)KP2);
}

// fused head: z = relu((x1+x2)@Wf + bf) ; out = z@Wf1 + bf1
__global__ void fchead_k(const float* __restrict__ x1, const float* __restrict__ x2,
                         const float* __restrict__ Wf, const float* __restrict__ bf,
                         const float* __restrict__ Wf1, const float* __restrict__ bf1,
                         float* __restrict__ out) {
    __shared__ float xs[HD];
    __shared__ float zs[FC1D];
    int m = blockIdx.x, c = threadIdx.x;
    xs[c]       = x1[m * HD + c]       + x2[m * HD + c];
    xs[c + 512] = x1[m * HD + c + 512] + x2[m * HD + c + 512];
    __syncthreads();
    float s = bf[c];
    #pragma unroll 4
    for (int k = 0; k < HD; k++) s += xs[k] * Wf[(size_t)k * FC1D + c];
    zs[c] = fmaxf(s, 0.f);
    __syncthreads();
    if (c < OUTD) {
        float o = bf1[c];
        #pragma unroll 4
        for (int k = 0; k < FC1D; k++) o += zs[k] * Wf1[k * OUTD + c];
        out[m * OUTD + c] = o;
    }
}

// ---------------- launch ----------------
extern "C" void kernel_launch(void* const* d_in, const int* in_sizes, int n_in,
                              void* d_out, int out_size) {
    (void)in_sizes; (void)n_in; (void)out_size;
    float* FS = nullptr; int* IS = nullptr;
    __nv_bfloat16 *a1s = nullptr, *w1s = nullptr, *a2s = nullptr, *w2s = nullptr;
    cudaGetSymbolAddress((void**)&FS, d_fscratch);
    cudaGetSymbolAddress((void**)&IS, d_iscratch);
    cudaGetSymbolAddress((void**)&a1s, d_a1s);
    cudaGetSymbolAddress((void**)&w1s, d_w1s);
    cudaGetSymbolAddress((void**)&a2s, d_a2s);
    cudaGetSymbolAddress((void**)&w2s, d_w2s);
    cudaFuncSetAttribute(gemm_mma, cudaFuncAttributeMaxDynamicSharedMemorySize, GEMM_SMEM_DYN);

    static cudaStream_t sB = nullptr;
    static cudaEvent_t eF = nullptr, eB1 = nullptr, eT1 = nullptr, eG1 = nullptr,
                       eB2 = nullptr, eMP = nullptr;
    if (!sB) {
        cudaStreamCreateWithFlags(&sB, cudaStreamNonBlocking);
        cudaEventCreateWithFlags(&eF,  cudaEventDisableTiming);
        cudaEventCreateWithFlags(&eB1, cudaEventDisableTiming);
        cudaEventCreateWithFlags(&eT1, cudaEventDisableTiming);
        cudaEventCreateWithFlags(&eG1, cudaEventDisableTiming);
        cudaEventCreateWithFlags(&eB2, cudaEventDisableTiming);
        cudaEventCreateWithFlags(&eMP, cudaEventDisableTiming);
    }

    const float* x   = (const float*)d_in[0];
    const int*   ei  = (const int*)d_in[1];
    const float* W1  = (const float*)d_in[3];
    const float* g1  = (const float*)d_in[5];
    const float* be1 = (const float*)d_in[6];
    const float* p1  = (const float*)d_in[7];
    const float* W2  = (const float*)d_in[8];
    const float* g2  = (const float*)d_in[10];
    const float* be2 = (const float*)d_in[11];
    const float* p2  = (const float*)d_in[12];
    const float* Wf  = (const float*)d_in[13];
    const float* bf  = (const float*)d_in[14];
    const float* Wf1 = (const float*)d_in[15];
    const float* bf1 = (const float*)d_in[16];
    float* out = (float*)d_out;

    const int* src = ei;
    const int* dst = ei + E_TOT;

    float* agg1  = FS + F_AGG1;
    float* hp1   = FS + F_HP1;
    float* agg2  = FS + F_AGG2;
    float* dinv1 = FS + F_DINV1;
    float* dinv2 = FS + F_DINV2;
    float* score1= FS + F_SCORE1;
    float* score2= FS + F_SCORE2;
    float* val1  = FS + F_VAL1;
    float* val2  = FS + F_VAL2;
    float* cols  = FS + F_COLS;
    float* csum1 = cols, *csq1 = cols + HD, *csum2 = cols + 2 * HD, *csq2 = cols + 3 * HD;
    float* scale = FS + F_SCALE;
    float* shift = FS + F_SHIFT;
    float* pn1   = FS + F_PN1;
    float* pn2   = FS + F_PN2;
    float* x1    = FS + F_X1;
    float* x2    = FS + F_X2;

    int* src2  = IS + I_SRC2;
    int* dst2  = IS + I_DST2;
    int* csr   = IS + I_CSR;
    int* cnt1  = IS + I_CNT1;
    int* cnt2  = IS + I_CNT2;
    int* off1  = IS + I_OFF1;
    int* cur1  = IS + I_CUR1;
    int* off2  = IS + I_OFF2;
    int* cur2  = IS + I_CUR2;
    int* perm1 = IS + I_PERM1;
    int* perm2 = IS + I_PERM2;
    int* newid = IS + I_NEWID;

    // ===== fork: side stream does weight splits + pnorms + colsum zero =====
    cudaEventRecord(eF, 0);
    cudaStreamWaitEvent(sB, eF, 0);
    wsplit_k<<<(F_IN * HD) / 256, 256, 0, sB>>>(W1, w1s, F_IN);
    wsplit_k<<<(HD * HD) / 256, 256, 0, sB>>>(W2, w2s, HD);
    fill_k<<<(4 * HD) / 256, 256, 0, sB>>>(cols, 4 * HD, 0.f);
    pnorm_k<<<1, HD, 0, sB>>>(p1, pn1);
    pnorm_k<<<1, HD, 0, sB>>>(p2, pn2);
    cudaEventRecord(eB1, sB);

    // ===== main: CSR1 -> gather+split(X) -> GEMM1 (direct agg1 + stats) =====
    zero_int_k<<<(N1 + N2 + 255) / 256, 256>>>(cnt1, N1 + N2);
    count_k<<<E_TOT / 256, 256>>>(dst, cnt1, E_TOT);
    scan_off_k<NPG><<<BG, NPG>>>(cnt1, off1, cur1, dinv1);
    fill_csr_k<<<E_TOT / 256, 256>>>(src, dst, cur1, csr, E_TOT, 0);
    gxsplit_k<<<N1, 128>>>(x, csr, off1, cnt1, dinv1, a1s);
    cudaStreamWaitEvent(0, eB1, 0);
    gemm_mma<<<dim3(HD / 128, N1 / 128), 128, GEMM_SMEM_DYN>>>(
        a1s, w1s, agg1, 3 * F_IN, 2 * F_IN, csum1, csq1);

    bnprep_k<<<HD / 256, 256>>>(csum1, csq1, 1.0f / (float)N1, g1, be1, scale, shift);
    score_k<<<N1, 256>>>(agg1, scale, shift, pn1, score1);
    topk_k<NPG, KP1><<<BG, NPG>>>(score1, val1, perm1, newid);
    cudaEventRecord(eT1, 0);

    // side: CSR for layer 2 (overlaps main's gather_bn)
    cudaStreamWaitEvent(sB, eT1, 0);
    remapcount_k<<<E_TOT / 256, 256, 0, sB>>>(src, dst, newid, src2, dst2, cnt2, E_TOT);
    scan_off_k<KP1><<<BG, KP1, 0, sB>>>(cnt2, off2, cur2, dinv2);
    fill_csr_k<<<E_TOT / 256, 256, 0, sB>>>(src2, dst2, cur2, csr, E_TOT, 1);
    cudaEventRecord(eB2, sB);

    gather_bn_k<<<N2, 256>>>(agg1, perm1, val1, scale, shift, hp1);
    cudaEventRecord(eG1, 0);
    // meanpool1 on side stream
    cudaStreamWaitEvent(sB, eG1, 0);
    meanpool_k<<<dim3(BG, HD / 256), 256, 0, sB>>>(hp1, x1, KP1);
    cudaEventRecord(eMP, sB);

    // ===== layer 2: gather(hp1)+split -> GEMM2 (direct agg2 + stats) =====
    cudaStreamWaitEvent(0, eB2, 0);
    y2split_k<<<N2, 256>>>(hp1, csr, off2, cnt2, dinv2, a2s);
    gemm_mma<<<dim3(HD / 128, N2 / 128), 128, GEMM_SMEM_DYN>>>(
        a2s, w2s, agg2, 3 * HD, 2 * HD, csum2, csq2);

    bnprep_k<<<HD / 256, 256>>>(csum2, csq2, 1.0f / (float)N2, g2, be2, scale, shift);
    score_k<<<N2, 256>>>(agg2, scale, shift, pn2, score2);
    topk_k<KP1, KP2><<<BG, KP1>>>(score2, val2, perm2, nullptr);
    gpool2_k<<<dim3(BG, HD / 256), 256>>>(agg2, perm2, val2, scale, shift, x2);

    // ===== Head (fused) =====
    cudaStreamWaitEvent(0, eMP, 0);
    fchead_k<<<BG, FC1D>>>(x1, x2, Wf, bf, Wf1, bf1, out);
}